// round 9
// baseline (speedup 1.0000x reference)
#include <cuda_runtime.h>
#include <cstdint>

#define NROWS  65536
#define DDIM   256
#define KCODES 1024
#define NTILES 512
#define MARGIN 2e-3f
#define FINF   3.4e38f

typedef unsigned int u32; typedef unsigned long long u64;

__device__ __align__(16) u32 gAq[NTILES * 64 * 128];  // [tile][k4][row] int8x4
__device__ __align__(16) u32 gBq[8 * 128 * 64];       // [chunk][code][k4]
__device__ float g_esq[KCODES];
__device__ float g_ce[KCODES];      // -2 * s_e
__device__ float g_zs[NROWS];       // s_z per row
__device__ int   g_idx[NROWS];
__device__ int   g_duel[NROWS];
__device__ int2  g_duelc[NROWS];
__device__ int   g_full[NROWS];
__device__ int   g_duel_n, g_full_n;
__device__ float g_partial[NTILES];

__device__ __forceinline__ u32 smem_u32(const void* p) {
    u32 a; asm("{ .reg .u64 t; cvta.to.shared.u64 t, %1; cvt.u32.u64 %0, t; }" : "=r"(a) : "l"(p));
    return a;
}
__device__ __forceinline__ void cpasync16(u32 dst, const void* src) {
    u64 g = (u64)__cvta_generic_to_global(src);
    asm volatile("cp.async.cg.shared.global [%0], [%1], 16;" :: "r"(dst), "l"(g) : "memory");
}
__device__ __forceinline__ int dp4a(u32 a, u32 b, int c) {
    int r;
    asm("dp4a.s32.s32 %0, %1, %2, %3;" : "=r"(r) : "r"(a), "r"(b), "r"(c));
    return r;
}
__device__ __forceinline__ u32 q4(float a, float b, float c, float d, float inv) {
    int qa = max(-127, min(127, __float2int_rn(a * inv)));
    int qb = max(-127, min(127, __float2int_rn(b * inv)));
    int qc = max(-127, min(127, __float2int_rn(c * inv)));
    int qd = max(-127, min(127, __float2int_rn(d * inv)));
    return (u32)(qa & 255) | ((u32)(qb & 255) << 8) | ((u32)(qc & 255) << 16) | ((u32)(qd & 255) << 24);
}

// ---------------- prep ----------------
// warp per row: scale + quantize z, write transposed [tile][k4][row]
__global__ void zquant_kernel(const float* __restrict__ z) {
    int w = (blockIdx.x * blockDim.x + threadIdx.x) >> 5, lane = threadIdx.x & 31;
    const float* row = z + (size_t)w * DDIM;
    float4 v0 = __ldg((const float4*)(row + lane * 8));
    float4 v1 = __ldg((const float4*)(row + lane * 8 + 4));
    float mx = fmaxf(fmaxf(fmaxf(fabsf(v0.x), fabsf(v0.y)), fmaxf(fabsf(v0.z), fabsf(v0.w))),
                     fmaxf(fmaxf(fabsf(v1.x), fabsf(v1.y)), fmaxf(fabsf(v1.z), fabsf(v1.w))));
    #pragma unroll
    for (int m = 16; m; m >>= 1) mx = fmaxf(mx, __shfl_xor_sync(0xffffffffu, mx, m));
    mx = fmaxf(mx, 1e-30f);
    float inv = 127.0f / mx;
    if (lane == 0) g_zs[w] = mx / 127.0f;
    u32 p0 = q4(v0.x, v0.y, v0.z, v0.w, inv);
    u32 p1 = q4(v1.x, v1.y, v1.z, v1.w, inv);
    int tile = w >> 7, rloc = w & 127;
    gAq[(tile * 64 + lane * 2 + 0) * 128 + rloc] = p0;
    gAq[(tile * 64 + lane * 2 + 1) * 128 + rloc] = p1;
}

// thread per code: EXACT serial esq (reference order) + scale; zero counters
__global__ void cbscale_kernel(const float* __restrict__ cb) {
    int k = blockIdx.x * blockDim.x + threadIdx.x;
    if (k == 0) { g_duel_n = 0; g_full_n = 0; }
    if (k >= KCODES) return;
    const float* row = cb + (size_t)k * DDIM;
    float s = 0.f, mx = 1e-30f;
    for (int d = 0; d < DDIM; d += 4) {
        float4 v = *(const float4*)&row[d];
        s = __fadd_rn(s, __fmul_rn(v.x, v.x)); s = __fadd_rn(s, __fmul_rn(v.y, v.y));
        s = __fadd_rn(s, __fmul_rn(v.z, v.z)); s = __fadd_rn(s, __fmul_rn(v.w, v.w));
        mx = fmaxf(mx, fmaxf(fmaxf(fabsf(v.x), fabsf(v.y)), fmaxf(fabsf(v.z), fabsf(v.w))));
    }
    g_esq[k] = s;
    g_ce[k] = -2.0f * (mx / 127.0f);
}

__global__ void cbquant_kernel(const float* __restrict__ cb) {
    int k = blockIdx.x * blockDim.x + threadIdx.x;
    if (k >= KCODES) return;
    const float* row = cb + (size_t)k * DDIM;
    float se = -0.5f * g_ce[k];
    float inv = 1.0f / se;
    int chunk = k >> 7, kloc = k & 127;
    u32* dst = gBq + (size_t)(chunk * 128 + kloc) * 64;
    for (int d = 0; d < DDIM; d += 4) {
        float4 v = *(const float4*)&row[d];
        dst[d >> 2] = q4(v.x, v.y, v.z, v.w, inv);
    }
}

// ---------------- main dp4a GEMM + top-3 ----------------
#define SM_A       0                         // 64*128*4 = 32768
#define SM_BST(s)  (32768 + (s) * 34816)     // 128 codes * 272B
#define SM_MRG     32768
#define SMEM_VQ    102400

__global__ __launch_bounds__(256, 1) void vq_kernel() {
    extern __shared__ unsigned char sm[];
    u32 sb = smem_u32(sm);
    const int t = threadIdx.x, tx = t & 15, ty = t >> 4;
    const int tile = blockIdx.x;

    for (int i = t; i < 2048; i += 256)
        cpasync16(sb + SM_A + i * 16, (const char*)gAq + (size_t)tile * 32768 + i * 16);
    for (int i = t; i < 2048; i += 256) {
        int code = i >> 4, cp = i & 15;
        cpasync16(sb + SM_BST(0) + code * 272 + cp * 16, (const char*)gBq + code * 256 + cp * 16);
    }
    asm volatile("cp.async.commit_group;" ::: "memory");

    float sz[8];
    #pragma unroll
    for (int i = 0; i < 8; i++) sz[i] = g_zs[tile * 128 + ty * 8 + i];
    float m1[8], m2[8], m3[8]; int i1[8], i2[8];
    #pragma unroll
    for (int i = 0; i < 8; i++) { m1[i] = FINF; m2[i] = FINF; m3[i] = FINF; i1[i] = 0x7fffffff; i2[i] = 0x7fffffff; }

    for (int c = 0; c < 8; c++) {
        asm volatile("cp.async.wait_group 0;" ::: "memory");
        __syncthreads();
        if (c < 7) {
            u32 dst = sb + SM_BST((c + 1) & 1);
            const char* src = (const char*)gBq + (size_t)(c + 1) * 32768;
            for (int i = t; i < 2048; i += 256) {
                int code = i >> 4, cp = i & 15;
                cpasync16(dst + code * 272 + cp * 16, src + code * 256 + cp * 16);
            }
            asm volatile("cp.async.commit_group;" ::: "memory");
        }
        int acc[8][8];
        #pragma unroll
        for (int i = 0; i < 8; i++)
            #pragma unroll
            for (int j = 0; j < 8; j++) acc[i][j] = 0;

        u32 bst = sb + SM_BST(c & 1);
        #pragma unroll 4
        for (int r = 0; r < 32; r++) {
            int k4 = r * 2;
            uint4 a0 = *(const uint4*)(sm + SM_A + k4 * 512 + ty * 32);
            uint4 a1 = *(const uint4*)(sm + SM_A + k4 * 512 + ty * 32 + 16);
            uint4 a2 = *(const uint4*)(sm + SM_A + (k4 + 1) * 512 + ty * 32);
            uint4 a3 = *(const uint4*)(sm + SM_A + (k4 + 1) * 512 + ty * 32 + 16);
            uint2 bp[8];
            #pragma unroll
            for (int j = 0; j < 8; j++)
                bp[j] = *(const uint2*)((const unsigned char*)sm + (bst - sb) + (tx + j * 16) * 272 + k4 * 4);
            u32 ar0[8] = {a0.x, a0.y, a0.z, a0.w, a1.x, a1.y, a1.z, a1.w};
            u32 ar1[8] = {a2.x, a2.y, a2.z, a2.w, a3.x, a3.y, a3.z, a3.w};
            #pragma unroll
            for (int j = 0; j < 8; j++)
                #pragma unroll
                for (int i = 0; i < 8; i++) {
                    acc[i][j] = dp4a(ar0[i], bp[j].x, acc[i][j]);
                    acc[i][j] = dp4a(ar1[i], bp[j].y, acc[i][j]);
                }
        }
        #pragma unroll
        for (int j = 0; j < 8; j++) {
            int code = c * 128 + tx + j * 16;
            float ce = __ldg(&g_ce[code]);
            float eq = __ldg(&g_esq[code]);
            #pragma unroll
            for (int i = 0; i < 8; i++) {
                float f = (float)acc[i][j];
                float d = fmaf(f * ce, sz[i], eq);
                bool p1 = d < m1[i], p2 = d < m2[i], p3 = d < m3[i];
                i2[i] = p1 ? i1[i] : (p2 ? code : i2[i]);
                i1[i] = p1 ? code : i1[i];
                m3[i] = p3 ? (p2 ? m2[i] : d) : m3[i];
                m2[i] = p2 ? (p1 ? m1[i] : d) : m2[i];
                m1[i] = p1 ? d : m1[i];
            }
        }
    }
    __syncthreads();
    float* rm1 = (float*)(sm + SM_MRG);
    float* rm2 = rm1 + 2048; float* rm3 = rm2 + 2048;
    int* ri1 = (int*)(rm3 + 2048); int* ri2 = ri1 + 2048;
    #pragma unroll
    for (int i = 0; i < 8; i++) {
        int s = (ty * 8 + i) * 16 + tx;
        rm1[s] = m1[i]; rm2[s] = m2[i]; rm3[s] = m3[i]; ri1[s] = i1[i]; ri2[s] = i2[i];
    }
    __syncthreads();
    if (t < 128) {
        float v1 = FINF, v2 = FINF, v3 = FINF; int a1 = 0x7fffffff, a2 = 0x7fffffff;
        for (int e = 0; e < 16; e++) {
            int s = t * 16 + e;
            float d; int cdx;
            d = rm1[s]; cdx = ri1[s];
            if (d < v1 || (d == v1 && cdx < a1)) { v3 = v2; v2 = v1; a2 = a1; v1 = d; a1 = cdx; }
            else if (d < v2 || (d == v2 && cdx < a2)) { v3 = v2; v2 = d; a2 = cdx; }
            else if (d < v3) v3 = d;
            d = rm2[s]; cdx = ri2[s];
            if (d < v1 || (d == v1 && cdx < a1)) { v3 = v2; v2 = v1; a2 = a1; v1 = d; a1 = cdx; }
            else if (d < v2 || (d == v2 && cdx < a2)) { v3 = v2; v2 = d; a2 = cdx; }
            else if (d < v3) v3 = d;
            d = rm3[s];
            if (d < v3) v3 = d;   // value-only third
        }
        int row = tile * 128 + t;
        g_idx[row] = a1;
        if (v2 - v1 <= MARGIN) {
            if (v3 - v1 > MARGIN) {
                int p = atomicAdd(&g_duel_n, 1); g_duel[p] = row; g_duelc[p] = make_int2(a1, a2);
            } else {
                int p = atomicAdd(&g_full_n, 1); g_full[p] = row;
            }
        }
    }
}

// ---------------- exact resolution ----------------
__global__ void duel_kernel(const float* __restrict__ z, const float* __restrict__ cb) {
    int n = g_duel_n;
    for (int a = blockIdx.x * blockDim.x + threadIdx.x; a < n; a += gridDim.x * blockDim.x) {
        int row = g_duel[a]; int2 cc = g_duelc[a];
        const float* zr = z + (size_t)row * DDIM;
        const float* ea = cb + (size_t)cc.x * DDIM;
        const float* eb = cb + (size_t)cc.y * DDIM;
        float ca = 0.f, cv = 0.f, zq = 0.f;
        for (int d = 0; d < DDIM; d += 4) {
            float4 zv = __ldg((const float4*)(zr + d));
            float4 av = __ldg((const float4*)(ea + d));
            float4 bv = __ldg((const float4*)(eb + d));
            zq = __fadd_rn(zq, __fmul_rn(zv.x, zv.x)); zq = __fadd_rn(zq, __fmul_rn(zv.y, zv.y));
            zq = __fadd_rn(zq, __fmul_rn(zv.z, zv.z)); zq = __fadd_rn(zq, __fmul_rn(zv.w, zv.w));
            ca = fmaf(zv.x, av.x, ca); cv = fmaf(zv.x, bv.x, cv);
            ca = fmaf(zv.y, av.y, ca); cv = fmaf(zv.y, bv.y, cv);
            ca = fmaf(zv.z, av.z, ca); cv = fmaf(zv.z, bv.z, cv);
            ca = fmaf(zv.w, av.w, ca); cv = fmaf(zv.w, bv.w, cv);
        }
        float da = __fadd_rn(__fsub_rn(zq, __fmul_rn(2.f, ca)), g_esq[cc.x]);
        float db = __fadd_rn(__fsub_rn(zq, __fmul_rn(2.f, cv)), g_esq[cc.y]);
        g_idx[row] = (db < da || (db == da && cc.y < cc.x)) ? cc.y : cc.x;
    }
}

__global__ __launch_bounds__(256) void fullscan_kernel(const float* __restrict__ z,
                                                       const float* __restrict__ cb) {
    __shared__ float zs[256 * 17];
    __shared__ float szq[16];
    __shared__ float sbv[128]; __shared__ int sbi[128];
    int n = g_full_n;
    int t = threadIdx.x, lane = t & 31, w = t >> 5;
    for (int tb = blockIdx.x; tb * 16 < n; tb += gridDim.x) {
        int cnt = min(16, n - tb * 16);
        __syncthreads();
        for (int r = 0; r < 16; r++) {
            if (r < cnt) zs[t * 17 + r] = z[(size_t)g_full[tb * 16 + r] * DDIM + t];
            else zs[t * 17 + r] = 0.f;
        }
        __syncthreads();
        if (t < 16) {   // exact serial z_sq
            float s = 0.f;
            for (int d = 0; d < DDIM; d++) {
                float v = zs[d * 17 + t];
                s = __fadd_rn(s, __fmul_rn(v, v));
            }
            szq[t] = s;
        }
        __syncthreads();
        int r = lane & 15, ks = lane >> 4;
        float zq = szq[r];
        float bv = FINF; int bi = 0x7fffffff;
        for (int j = 0; j < 64; j++) {
            int k = j * 16 + w * 2 + ks;
            const float* er = cb + (size_t)k * DDIM;
            float c = 0.f;
            for (int d = 0; d < DDIM; d += 4) {
                float4 ev = __ldg((const float4*)(er + d));
                c = fmaf(zs[(d + 0) * 17 + r], ev.x, c);
                c = fmaf(zs[(d + 1) * 17 + r], ev.y, c);
                c = fmaf(zs[(d + 2) * 17 + r], ev.z, c);
                c = fmaf(zs[(d + 3) * 17 + r], ev.w, c);
            }
            float dist = __fadd_rn(__fsub_rn(zq, __fmul_rn(2.f, c)), __ldg(&g_esq[k]));
            if (dist < bv || (dist == bv && k < bi)) { bv = dist; bi = k; }
        }
        {   // merge ks pair (same r)
            float ov = __shfl_xor_sync(0xffffffffu, bv, 16);
            int   oi = __shfl_xor_sync(0xffffffffu, bi, 16);
            if (ov < bv || (ov == bv && oi < bi)) { bv = ov; bi = oi; }
        }
        if (ks == 0) { sbv[w * 16 + r] = bv; sbi[w * 16 + r] = bi; }
        __syncthreads();
        if (t < cnt) {
            float fv = sbv[t]; int fi = sbi[t];
            #pragma unroll
            for (int ww = 1; ww < 8; ww++) {
                float ov = sbv[ww * 16 + t]; int oi = sbi[ww * 16 + t];
                if (ov < fv || (ov == fv && oi < fi)) { fv = ov; fi = oi; }
            }
            g_idx[g_full[tb * 16 + t]] = fi;
        }
    }
}

// ---------------- gather + loss ----------------
__global__ __launch_bounds__(256) void gather_kernel(const float* __restrict__ z,
                                                     const float* __restrict__ cb,
                                                     float* __restrict__ out) {
    __shared__ int sidx[128]; __shared__ float red[256];
    int t = threadIdx.x, rowbase = blockIdx.x * 128;
    if (t < 128) sidx[t] = g_idx[rowbase + t];
    __syncthreads();
    float lsum = 0.f;
    for (int r = 0; r < 128; r++) {
        int idx = sidx[r];
        float zq = cb[(size_t)idx * DDIM + t];
        float ze = z[(size_t)(rowbase + r) * DDIM + t];
        out[(size_t)(rowbase + r) * DDIM + t] = zq;
        float df = zq - ze; lsum = fmaf(df, df, lsum);
    }
    red[t] = lsum; __syncthreads();
    for (int s = 128; s; s >>= 1) { if (t < s) red[t] += red[t + s]; __syncthreads(); }
    if (t == 0) g_partial[blockIdx.x] = red[0];
}

__global__ void finalize_kernel(float* __restrict__ out, int out_size) {
    __shared__ float red[512];
    int t = threadIdx.x;
    red[t] = g_partial[t];
    __syncthreads();
    for (int s = 256; s; s >>= 1) { if (t < s) red[t] += red[t + s]; __syncthreads(); }
    float loss = red[0] / (float)((long long)NROWS * DDIM);
    const long long base = (long long)NROWS * DDIM;
    for (long long i = base + t; i < (long long)out_size; i += blockDim.x) out[i] = loss;
}

extern "C" void kernel_launch(void* const* d_in, const int* in_sizes, int n_in,
                              void* d_out, int out_size) {
    const float* z  = (const float*)d_in[0];
    const float* cb = (const float*)d_in[1];
    if (n_in >= 2 && in_sizes[0] == KCODES * DDIM && in_sizes[1] == NROWS * DDIM) {
        z = (const float*)d_in[1]; cb = (const float*)d_in[0];
    }
    float* out = (float*)d_out;
    cudaFuncSetAttribute(vq_kernel, cudaFuncAttributeMaxDynamicSharedMemorySize, SMEM_VQ);

    zquant_kernel<<<2048, 256>>>(z);
    cbscale_kernel<<<4, 256>>>(cb);
    cbquant_kernel<<<4, 256>>>(cb);
    vq_kernel<<<NTILES, 256, SMEM_VQ>>>();
    duel_kernel<<<128, 256>>>(z, cb);
    fullscan_kernel<<<148, 256>>>(z, cb);
    gather_kernel<<<512, 256>>>(z, cb, out);
    finalize_kernel<<<1, 512>>>(out, out_size);
}

// round 11
// speedup vs baseline: 8.5330x; 8.5330x over previous
#include <cuda_runtime.h>
#include <cstdint>

#define NROWS  65536
#define DDIM   256
#define KCODES 1024
#define NTILES 512
#define MARGIN 2e-3f
#define FINF   3.4e38f

typedef unsigned int u32; typedef unsigned long long u64;

__device__ __align__(16) u32 gAq[NTILES * 64 * 128];  // [tile][k4][row] int8x4
__device__ __align__(16) u32 gBq[16 * 64 * 64];       // [chunk64][k4][code] int8x4
__device__ float g_esq[KCODES];
__device__ float g_ce[KCODES];      // -2 * s_e
__device__ float g_zs[NROWS];       // s_z per row
__device__ int   g_idx[NROWS];
__device__ int   g_duel[NROWS];
__device__ int2  g_duelc[NROWS];
__device__ int   g_full[NROWS];
__device__ int   g_duel_n, g_full_n;
__device__ float g_partial[NTILES];

__device__ __forceinline__ u32 smem_u32(const void* p) {
    u32 a; asm("{ .reg .u64 t; cvta.to.shared.u64 t, %1; cvt.u32.u64 %0, t; }" : "=r"(a) : "l"(p));
    return a;
}
__device__ __forceinline__ void cpasync16(u32 dst, const void* src) {
    u64 g = (u64)__cvta_generic_to_global(src);
    asm volatile("cp.async.cg.shared.global [%0], [%1], 16;" :: "r"(dst), "l"(g) : "memory");
}
__device__ __forceinline__ int dp4a(u32 a, u32 b, int c) {
    int r;
    asm("dp4a.s32.s32 %0, %1, %2, %3;" : "=r"(r) : "r"(a), "r"(b), "r"(c));
    return r;
}
__device__ __forceinline__ u32 q4(float a, float b, float c, float d, float inv) {
    int qa = max(-127, min(127, __float2int_rn(a * inv)));
    int qb = max(-127, min(127, __float2int_rn(b * inv)));
    int qc = max(-127, min(127, __float2int_rn(c * inv)));
    int qd = max(-127, min(127, __float2int_rn(d * inv)));
    return (u32)(qa & 255) | ((u32)(qb & 255) << 8) | ((u32)(qc & 255) << 16) | ((u32)(qd & 255) << 24);
}

// ---------------- prep ----------------
// warp per row (65536 warps -> 8192 blocks)
__global__ void zquant_kernel(const float* __restrict__ z) {
    int w = (blockIdx.x * blockDim.x + threadIdx.x) >> 5, lane = threadIdx.x & 31;
    const float* row = z + (size_t)w * DDIM;
    float4 v0 = __ldg((const float4*)(row + lane * 8));
    float4 v1 = __ldg((const float4*)(row + lane * 8 + 4));
    float mx = fmaxf(fmaxf(fmaxf(fabsf(v0.x), fabsf(v0.y)), fmaxf(fabsf(v0.z), fabsf(v0.w))),
                     fmaxf(fmaxf(fabsf(v1.x), fabsf(v1.y)), fmaxf(fabsf(v1.z), fabsf(v1.w))));
    #pragma unroll
    for (int m = 16; m; m >>= 1) mx = fmaxf(mx, __shfl_xor_sync(0xffffffffu, mx, m));
    mx = fmaxf(mx, 1e-30f);
    float inv = 127.0f / mx;
    if (lane == 0) g_zs[w] = mx / 127.0f;
    u32 p0 = q4(v0.x, v0.y, v0.z, v0.w, inv);
    u32 p1 = q4(v1.x, v1.y, v1.z, v1.w, inv);
    int tile = w >> 7, rloc = w & 127;
    gAq[(tile * 64 + lane * 2 + 0) * 128 + rloc] = p0;
    gAq[(tile * 64 + lane * 2 + 1) * 128 + rloc] = p1;
}

// thread per code: EXACT serial esq (reference order) + scale; zero counters
__global__ void cbscale_kernel(const float* __restrict__ cb) {
    int k = blockIdx.x * blockDim.x + threadIdx.x;
    if (k == 0) { g_duel_n = 0; g_full_n = 0; }
    if (k >= KCODES) return;
    const float* row = cb + (size_t)k * DDIM;
    float s = 0.f, mx = 1e-30f;
    for (int d = 0; d < DDIM; d += 4) {
        float4 v = *(const float4*)&row[d];
        s = __fadd_rn(s, __fmul_rn(v.x, v.x)); s = __fadd_rn(s, __fmul_rn(v.y, v.y));
        s = __fadd_rn(s, __fmul_rn(v.z, v.z)); s = __fadd_rn(s, __fmul_rn(v.w, v.w));
        mx = fmaxf(mx, fmaxf(fmaxf(fabsf(v.x), fabsf(v.y)), fmaxf(fabsf(v.z), fabsf(v.w))));
    }
    g_esq[k] = s;
    g_ce[k] = -2.0f * (mx / 127.0f);
}

// transposed B: [chunk64][k4][code]
__global__ void cbquant_kernel(const float* __restrict__ cb) {
    int k = blockIdx.x * blockDim.x + threadIdx.x;
    if (k >= KCODES) return;
    const float* row = cb + (size_t)k * DDIM;
    float inv = 1.0f / (-0.5f * g_ce[k]);
    int chunk = k >> 6, kloc = k & 63;
    for (int d = 0; d < DDIM; d += 4) {
        float4 v = *(const float4*)&row[d];
        gBq[(chunk * 64 + (d >> 2)) * 64 + kloc] = q4(v.x, v.y, v.z, v.w, inv);
    }
}

// ---------------- main dp4a GEMM + top-3 ----------------
#define SM_A     0                        // 64 k4 x 128 rows x 4B = 32768
#define SM_B(s)  (32768 + (s) * 16384)    // 64 k4 x 64 codes x 4B
#define SM_MRG   0                        // overlay after compute
#define SMEM_VQ  65536

__global__ __launch_bounds__(256, 2) void vq_kernel() {
    extern __shared__ unsigned char sm[];
    u32 sb = smem_u32(sm);
    const int t = threadIdx.x, tx = t & 15, ty = t >> 4;
    const int tile = blockIdx.x;

    // A (32KB) + B chunk 0 (16KB) in group G0
    for (int i = t; i < 2048; i += 256)
        cpasync16(sb + SM_A + i * 16, (const char*)gAq + (size_t)tile * 32768 + i * 16);
    for (int i = t; i < 1024; i += 256)
        cpasync16(sb + SM_B(0) + i * 16, (const char*)gBq + i * 16);
    asm volatile("cp.async.commit_group;" ::: "memory");

    float sz[8];
    #pragma unroll
    for (int i = 0; i < 8; i++) sz[i] = g_zs[tile * 128 + ty * 8 + i];
    float m1[8], m2[8], m3[8]; int i1[8], i2[8];
    #pragma unroll
    for (int i = 0; i < 8; i++) { m1[i] = FINF; m2[i] = FINF; m3[i] = FINF; i1[i] = 0x7fffffff; i2[i] = 0x7fffffff; }

    for (int c = 0; c < 16; c++) {
        // R10 bug fix: issue prefetch(c+1) BEFORE wait_group 1, so the wait
        // actually covers G_c (the chunk we are about to read).
        if (c < 15) {
            u32 dst = sb + SM_B((c + 1) & 1);
            const char* src = (const char*)gBq + (size_t)(c + 1) * 16384;
            for (int i = t; i < 1024; i += 256) cpasync16(dst + i * 16, src + i * 16);
            asm volatile("cp.async.commit_group;" ::: "memory");
            asm volatile("cp.async.wait_group 1;" ::: "memory");
        } else {
            asm volatile("cp.async.wait_group 0;" ::: "memory");
        }
        __syncthreads();

        int acc[8][4];
        #pragma unroll
        for (int i = 0; i < 8; i++)
            #pragma unroll
            for (int j = 0; j < 4; j++) acc[i][j] = 0;

        u32 bst = sb + SM_B(c & 1);
        #pragma unroll 4
        for (int r = 0; r < 32; r++) {
            int k4 = r * 2;
            uint4 a0 = *(const uint4*)(sm + SM_A + k4 * 512 + ty * 32);
            uint4 a1 = *(const uint4*)(sm + SM_A + k4 * 512 + ty * 32 + 16);
            uint4 a2 = *(const uint4*)(sm + SM_A + (k4 + 1) * 512 + ty * 32);
            uint4 a3 = *(const uint4*)(sm + SM_A + (k4 + 1) * 512 + ty * 32 + 16);
            u32 b0[4], b1[4];
            #pragma unroll
            for (int j = 0; j < 4; j++) {
                b0[j] = *(const u32*)((const unsigned char*)sm + (bst - sb) + k4 * 256 + (tx + j * 16) * 4);
                b1[j] = *(const u32*)((const unsigned char*)sm + (bst - sb) + (k4 + 1) * 256 + (tx + j * 16) * 4);
            }
            u32 ar0[8] = {a0.x, a0.y, a0.z, a0.w, a1.x, a1.y, a1.z, a1.w};
            u32 ar1[8] = {a2.x, a2.y, a2.z, a2.w, a3.x, a3.y, a3.z, a3.w};
            #pragma unroll
            for (int j = 0; j < 4; j++)
                #pragma unroll
                for (int i = 0; i < 8; i++) {
                    acc[i][j] = dp4a(ar0[i], b0[j], acc[i][j]);
                    acc[i][j] = dp4a(ar1[i], b1[j], acc[i][j]);
                }
        }
        #pragma unroll
        for (int j = 0; j < 4; j++) {
            int code = c * 64 + tx + j * 16;
            float ce = __ldg(&g_ce[code]);
            float eq = __ldg(&g_esq[code]);
            #pragma unroll
            for (int i = 0; i < 8; i++) {
                float f = (float)acc[i][j];
                float d = fmaf(f * ce, sz[i], eq);
                bool p1 = d < m1[i], p2 = d < m2[i], p3 = d < m3[i];
                i2[i] = p1 ? i1[i] : (p2 ? code : i2[i]);
                i1[i] = p1 ? code : i1[i];
                m3[i] = p3 ? (p2 ? m2[i] : d) : m3[i];
                m2[i] = p2 ? (p1 ? m1[i] : d) : m2[i];
                m1[i] = p1 ? d : m1[i];
            }
        }
        __syncthreads();   // stage c&1 fully read before it can be overwritten
    }
    float* rm1 = (float*)(sm + SM_MRG);
    float* rm2 = rm1 + 2048; float* rm3 = rm2 + 2048;
    int* ri1 = (int*)(rm3 + 2048); int* ri2 = ri1 + 2048;
    #pragma unroll
    for (int i = 0; i < 8; i++) {
        int s = (ty * 8 + i) * 16 + tx;
        rm1[s] = m1[i]; rm2[s] = m2[i]; rm3[s] = m3[i]; ri1[s] = i1[i]; ri2[s] = i2[i];
    }
    __syncthreads();
    if (t < 128) {
        float v1 = FINF, v2 = FINF, v3 = FINF; int a1 = 0x7fffffff, a2 = 0x7fffffff;
        for (int e = 0; e < 16; e++) {
            int s = t * 16 + e;
            float d; int cdx;
            d = rm1[s]; cdx = ri1[s];
            if (d < v1 || (d == v1 && cdx < a1)) { v3 = v2; v2 = v1; a2 = a1; v1 = d; a1 = cdx; }
            else if (d < v2 || (d == v2 && cdx < a2)) { v3 = v2; v2 = d; a2 = cdx; }
            else if (d < v3) v3 = d;
            d = rm2[s]; cdx = ri2[s];
            if (d < v1 || (d == v1 && cdx < a1)) { v3 = v2; v2 = v1; a2 = a1; v1 = d; a1 = cdx; }
            else if (d < v2 || (d == v2 && cdx < a2)) { v3 = v2; v2 = d; a2 = cdx; }
            else if (d < v3) v3 = d;
            d = rm3[s];
            if (d < v3) v3 = d;
        }
        int row = tile * 128 + t;
        g_idx[row] = a1;
        if (v2 - v1 <= MARGIN) {
            if (v3 - v1 > MARGIN) {
                int p = atomicAdd(&g_duel_n, 1); g_duel[p] = row; g_duelc[p] = make_int2(a1, a2);
            } else {
                int p = atomicAdd(&g_full_n, 1); g_full[p] = row;
            }
        }
    }
}

// ---------------- exact resolution ----------------
__global__ void duel_kernel(const float* __restrict__ z, const float* __restrict__ cb) {
    int n = g_duel_n;
    for (int a = blockIdx.x * blockDim.x + threadIdx.x; a < n; a += gridDim.x * blockDim.x) {
        int row = g_duel[a]; int2 cc = g_duelc[a];
        const float* zr = z + (size_t)row * DDIM;
        const float* ea = cb + (size_t)cc.x * DDIM;
        const float* eb = cb + (size_t)cc.y * DDIM;
        float ca = 0.f, cv = 0.f, zq = 0.f;
        for (int d = 0; d < DDIM; d += 4) {
            float4 zv = __ldg((const float4*)(zr + d));
            float4 av = __ldg((const float4*)(ea + d));
            float4 bv = __ldg((const float4*)(eb + d));
            zq = __fadd_rn(zq, __fmul_rn(zv.x, zv.x)); zq = __fadd_rn(zq, __fmul_rn(zv.y, zv.y));
            zq = __fadd_rn(zq, __fmul_rn(zv.z, zv.z)); zq = __fadd_rn(zq, __fmul_rn(zv.w, zv.w));
            ca = fmaf(zv.x, av.x, ca); cv = fmaf(zv.x, bv.x, cv);
            ca = fmaf(zv.y, av.y, ca); cv = fmaf(zv.y, bv.y, cv);
            ca = fmaf(zv.z, av.z, ca); cv = fmaf(zv.z, bv.z, cv);
            ca = fmaf(zv.w, av.w, ca); cv = fmaf(zv.w, bv.w, cv);
        }
        float da = __fadd_rn(__fsub_rn(zq, __fmul_rn(2.f, ca)), g_esq[cc.x]);
        float db = __fadd_rn(__fsub_rn(zq, __fmul_rn(2.f, cv)), g_esq[cc.y]);
        g_idx[row] = (db < da || (db == da && cc.y < cc.x)) ? cc.y : cc.x;
    }
}

// exact full scan, 8 rows/tile
__global__ __launch_bounds__(256) void fullscan_kernel(const float* __restrict__ z,
                                                       const float* __restrict__ cb) {
    __shared__ float zs[256 * 9];
    __shared__ float szq[8];
    __shared__ float sbv[64]; __shared__ int sbi[64];
    int n = g_full_n;
    int t = threadIdx.x, lane = t & 31, w = t >> 5;
    for (int tb = blockIdx.x; tb * 8 < n; tb += gridDim.x) {
        int cnt = min(8, n - tb * 8);
        __syncthreads();
        for (int r = 0; r < 8; r++) {
            if (r < cnt) zs[t * 9 + r] = z[(size_t)g_full[tb * 8 + r] * DDIM + t];
            else zs[t * 9 + r] = 0.f;
        }
        __syncthreads();
        if (t < 8) {   // exact serial z_sq
            float s = 0.f;
            for (int d = 0; d < DDIM; d++) {
                float v = zs[d * 9 + t];
                s = __fadd_rn(s, __fmul_rn(v, v));
            }
            szq[t] = s;
        }
        __syncthreads();
        int r = lane & 7, ks = lane >> 3;
        float zq = szq[r];
        float bv = FINF; int bi = 0x7fffffff;
        for (int j = 0; j < 32; j++) {
            int k = j * 32 + w * 4 + ks;
            const float* er = cb + (size_t)k * DDIM;
            float c = 0.f;
            for (int d = 0; d < DDIM; d += 4) {
                float4 ev = __ldg((const float4*)(er + d));
                c = fmaf(zs[(d + 0) * 9 + r], ev.x, c);
                c = fmaf(zs[(d + 1) * 9 + r], ev.y, c);
                c = fmaf(zs[(d + 2) * 9 + r], ev.z, c);
                c = fmaf(zs[(d + 3) * 9 + r], ev.w, c);
            }
            float dist = __fadd_rn(__fsub_rn(zq, __fmul_rn(2.f, c)), __ldg(&g_esq[k]));
            if (dist < bv || (dist == bv && k < bi)) { bv = dist; bi = k; }
        }
        #pragma unroll
        for (int msk = 8; msk <= 16; msk <<= 1) {
            float ov = __shfl_xor_sync(0xffffffffu, bv, msk);
            int   oi = __shfl_xor_sync(0xffffffffu, bi, msk);
            if (ov < bv || (ov == bv && oi < bi)) { bv = ov; bi = oi; }
        }
        if (ks == 0) { sbv[w * 8 + r] = bv; sbi[w * 8 + r] = bi; }
        __syncthreads();
        if (t < cnt) {
            float fv = sbv[t]; int fi = sbi[t];
            #pragma unroll
            for (int ww = 1; ww < 8; ww++) {
                float ov = sbv[ww * 8 + t]; int oi = sbi[ww * 8 + t];
                if (ov < fv || (ov == fv && oi < fi)) { fv = ov; fi = oi; }
            }
            g_idx[g_full[tb * 8 + t]] = fi;
        }
    }
}

// ---------------- gather + loss ----------------
__global__ __launch_bounds__(256) void gather_kernel(const float* __restrict__ z,
                                                     const float* __restrict__ cb,
                                                     float* __restrict__ out) {
    __shared__ int sidx[128]; __shared__ float red[256];
    int t = threadIdx.x, rowbase = blockIdx.x * 128;
    if (t < 128) sidx[t] = g_idx[rowbase + t];
    __syncthreads();
    float lsum = 0.f;
    for (int r = 0; r < 128; r++) {
        int idx = sidx[r];
        float zq = cb[(size_t)idx * DDIM + t];
        float ze = z[(size_t)(rowbase + r) * DDIM + t];
        out[(size_t)(rowbase + r) * DDIM + t] = zq;
        float df = zq - ze; lsum = fmaf(df, df, lsum);
    }
    red[t] = lsum; __syncthreads();
    for (int s = 128; s; s >>= 1) { if (t < s) red[t] += red[t + s]; __syncthreads(); }
    if (t == 0) g_partial[blockIdx.x] = red[0];
}

__global__ void finalize_kernel(float* __restrict__ out, int out_size) {
    __shared__ float red[512];
    int t = threadIdx.x;
    red[t] = g_partial[t];
    __syncthreads();
    for (int s = 256; s; s >>= 1) { if (t < s) red[t] += red[t + s]; __syncthreads(); }
    float loss = red[0] / (float)((long long)NROWS * DDIM);
    const long long base = (long long)NROWS * DDIM;
    for (long long i = base + t; i < (long long)out_size; i += blockDim.x) out[i] = loss;
}

extern "C" void kernel_launch(void* const* d_in, const int* in_sizes, int n_in,
                              void* d_out, int out_size) {
    const float* z  = (const float*)d_in[0];
    const float* cb = (const float*)d_in[1];
    if (n_in >= 2 && in_sizes[0] == KCODES * DDIM && in_sizes[1] == NROWS * DDIM) {
        z = (const float*)d_in[1]; cb = (const float*)d_in[0];
    }
    float* out = (float*)d_out;
    cudaFuncSetAttribute(vq_kernel, cudaFuncAttributeMaxDynamicSharedMemorySize, SMEM_VQ);

    zquant_kernel<<<8192, 256>>>(z);
    cbscale_kernel<<<4, 256>>>(cb);
    cbquant_kernel<<<4, 256>>>(cb);
    vq_kernel<<<NTILES, 256, SMEM_VQ>>>();
    duel_kernel<<<256, 256>>>(z, cb);
    fullscan_kernel<<<296, 256>>>(z, cb);
    gather_kernel<<<512, 256>>>(z, cb, out);
    finalize_kernel<<<1, 512>>>(out, out_size);
}

// round 12
// speedup vs baseline: 10.0051x; 1.1725x over previous
#include <cuda_runtime.h>
#include <cstdint>

#define NROWS  65536
#define DDIM   256
#define KCODES 1024
#define NTILES 512
#define MARGIN 2e-3f
#define FINF   3.4e38f

typedef unsigned int u32; typedef unsigned long long u64;

__device__ __align__(16) u32 gAq[NTILES * 64 * 128];  // [tile][k4][row] int8x4
__device__ __align__(16) u32 gBq[16 * 64 * 64];       // [chunk64][k4][code] int8x4
__device__ float g_esq[KCODES];
__device__ float g_ce[KCODES];      // -2 * s_e
__device__ float g_zs[NROWS];       // s_z per row
__device__ int   g_idx[NROWS];
__device__ int   g_duel[NROWS];
__device__ int2  g_duelc[NROWS];
__device__ int   g_full[NROWS];
__device__ int   g_duel_n, g_full_n;
__device__ float g_partial[NTILES];

__device__ __forceinline__ u32 smem_u32(const void* p) {
    u32 a; asm("{ .reg .u64 t; cvta.to.shared.u64 t, %1; cvt.u32.u64 %0, t; }" : "=r"(a) : "l"(p));
    return a;
}
__device__ __forceinline__ void cpasync16(u32 dst, const void* src) {
    u64 g = (u64)__cvta_generic_to_global(src);
    asm volatile("cp.async.cg.shared.global [%0], [%1], 16;" :: "r"(dst), "l"(g) : "memory");
}
__device__ __forceinline__ int dp4a(u32 a, u32 b, int c) {
    int r;
    asm("dp4a.s32.s32 %0, %1, %2, %3;" : "=r"(r) : "r"(a), "r"(b), "r"(c));
    return r;
}
__device__ __forceinline__ u32 q4(float a, float b, float c, float d, float inv) {
    int qa = max(-127, min(127, __float2int_rn(a * inv)));
    int qb = max(-127, min(127, __float2int_rn(b * inv)));
    int qc = max(-127, min(127, __float2int_rn(c * inv)));
    int qd = max(-127, min(127, __float2int_rn(d * inv)));
    return (u32)(qa & 255) | ((u32)(qb & 255) << 8) | ((u32)(qc & 255) << 16) | ((u32)(qd & 255) << 24);
}

// ---------------- prep ----------------
// warp per row (65536 warps -> 8192 blocks)
__global__ void zquant_kernel(const float* __restrict__ z) {
    int w = (blockIdx.x * blockDim.x + threadIdx.x) >> 5, lane = threadIdx.x & 31;
    const float* row = z + (size_t)w * DDIM;
    float4 v0 = __ldg((const float4*)(row + lane * 8));
    float4 v1 = __ldg((const float4*)(row + lane * 8 + 4));
    float mx = fmaxf(fmaxf(fmaxf(fabsf(v0.x), fabsf(v0.y)), fmaxf(fabsf(v0.z), fabsf(v0.w))),
                     fmaxf(fmaxf(fabsf(v1.x), fabsf(v1.y)), fmaxf(fabsf(v1.z), fabsf(v1.w))));
    #pragma unroll
    for (int m = 16; m; m >>= 1) mx = fmaxf(mx, __shfl_xor_sync(0xffffffffu, mx, m));
    mx = fmaxf(mx, 1e-30f);
    float inv = 127.0f / mx;
    if (lane == 0) g_zs[w] = mx / 127.0f;
    u32 p0 = q4(v0.x, v0.y, v0.z, v0.w, inv);
    u32 p1 = q4(v1.x, v1.y, v1.z, v1.w, inv);
    int tile = w >> 7, rloc = w & 127;
    gAq[(tile * 64 + lane * 2 + 0) * 128 + rloc] = p0;
    gAq[(tile * 64 + lane * 2 + 1) * 128 + rloc] = p1;
}

// thread per code: EXACT serial esq (reference order) + scale; zero counters
__global__ void cbscale_kernel(const float* __restrict__ cb) {
    int k = blockIdx.x * blockDim.x + threadIdx.x;
    if (k == 0) { g_duel_n = 0; g_full_n = 0; }
    if (k >= KCODES) return;
    const float* row = cb + (size_t)k * DDIM;
    float s = 0.f, mx = 1e-30f;
    for (int d = 0; d < DDIM; d += 4) {
        float4 v = *(const float4*)&row[d];
        s = __fadd_rn(s, __fmul_rn(v.x, v.x)); s = __fadd_rn(s, __fmul_rn(v.y, v.y));
        s = __fadd_rn(s, __fmul_rn(v.z, v.z)); s = __fadd_rn(s, __fmul_rn(v.w, v.w));
        mx = fmaxf(mx, fmaxf(fmaxf(fabsf(v.x), fabsf(v.y)), fmaxf(fabsf(v.z), fabsf(v.w))));
    }
    g_esq[k] = s;
    g_ce[k] = -2.0f * (mx / 127.0f);
}

// transposed B: [chunk64][k4][code]
__global__ void cbquant_kernel(const float* __restrict__ cb) {
    int k = blockIdx.x * blockDim.x + threadIdx.x;
    if (k >= KCODES) return;
    const float* row = cb + (size_t)k * DDIM;
    float inv = 1.0f / (-0.5f * g_ce[k]);
    int chunk = k >> 6, kloc = k & 63;
    for (int d = 0; d < DDIM; d += 4) {
        float4 v = *(const float4*)&row[d];
        gBq[(chunk * 64 + (d >> 2)) * 64 + kloc] = q4(v.x, v.y, v.z, v.w, inv);
    }
}

// ---------------- main dp4a GEMM + top-3 ----------------
#define SM_A     0                        // 64 k4 x 128 rows x 4B = 32768
#define SM_B(s)  (32768 + (s) * 16384)    // 64 k4 x 64 codes x 4B
#define SM_MRG   0                        // overlay after compute
#define SMEM_VQ  65536

__global__ __launch_bounds__(256, 2) void vq_kernel() {
    extern __shared__ unsigned char sm[];
    u32 sb = smem_u32(sm);
    const int t = threadIdx.x, tx = t & 15, ty = t >> 4;
    const int tile = blockIdx.x;

    // A (32KB) + B chunk 0 (16KB) in group G0
    for (int i = t; i < 2048; i += 256)
        cpasync16(sb + SM_A + i * 16, (const char*)gAq + (size_t)tile * 32768 + i * 16);
    for (int i = t; i < 1024; i += 256)
        cpasync16(sb + SM_B(0) + i * 16, (const char*)gBq + i * 16);
    asm volatile("cp.async.commit_group;" ::: "memory");

    float sz[8];
    #pragma unroll
    for (int i = 0; i < 8; i++) sz[i] = g_zs[tile * 128 + ty * 8 + i];
    float m1[8], m2[8], m3[8]; int i1[8], i2[8];
    #pragma unroll
    for (int i = 0; i < 8; i++) { m1[i] = FINF; m2[i] = FINF; m3[i] = FINF; i1[i] = 0x7fffffff; i2[i] = 0x7fffffff; }

    for (int c = 0; c < 16; c++) {
        // prefetch(c+1) BEFORE wait_group 1, so the wait covers G_c.
        if (c < 15) {
            u32 dst = sb + SM_B((c + 1) & 1);
            const char* src = (const char*)gBq + (size_t)(c + 1) * 16384;
            for (int i = t; i < 1024; i += 256) cpasync16(dst + i * 16, src + i * 16);
            asm volatile("cp.async.commit_group;" ::: "memory");
            asm volatile("cp.async.wait_group 1;" ::: "memory");
        } else {
            asm volatile("cp.async.wait_group 0;" ::: "memory");
        }
        __syncthreads();

        int acc[8][4];
        #pragma unroll
        for (int i = 0; i < 8; i++)
            #pragma unroll
            for (int j = 0; j < 4; j++) acc[i][j] = 0;

        u32 bst = sb + SM_B(c & 1);
        #pragma unroll 4
        for (int r = 0; r < 32; r++) {
            int k4 = r * 2;
            uint4 a0 = *(const uint4*)(sm + SM_A + k4 * 512 + ty * 32);
            uint4 a1 = *(const uint4*)(sm + SM_A + k4 * 512 + ty * 32 + 16);
            uint4 a2 = *(const uint4*)(sm + SM_A + (k4 + 1) * 512 + ty * 32);
            uint4 a3 = *(const uint4*)(sm + SM_A + (k4 + 1) * 512 + ty * 32 + 16);
            u32 b0[4], b1[4];
            #pragma unroll
            for (int j = 0; j < 4; j++) {
                b0[j] = *(const u32*)((const unsigned char*)sm + (bst - sb) + k4 * 256 + (tx + j * 16) * 4);
                b1[j] = *(const u32*)((const unsigned char*)sm + (bst - sb) + (k4 + 1) * 256 + (tx + j * 16) * 4);
            }
            u32 ar0[8] = {a0.x, a0.y, a0.z, a0.w, a1.x, a1.y, a1.z, a1.w};
            u32 ar1[8] = {a2.x, a2.y, a2.z, a2.w, a3.x, a3.y, a3.z, a3.w};
            #pragma unroll
            for (int j = 0; j < 4; j++)
                #pragma unroll
                for (int i = 0; i < 8; i++) {
                    acc[i][j] = dp4a(ar0[i], b0[j], acc[i][j]);
                    acc[i][j] = dp4a(ar1[i], b1[j], acc[i][j]);
                }
        }
        #pragma unroll
        for (int j = 0; j < 4; j++) {
            int code = c * 64 + tx + j * 16;
            float ce = __ldg(&g_ce[code]);
            float eq = __ldg(&g_esq[code]);
            #pragma unroll
            for (int i = 0; i < 8; i++) {
                float f = (float)acc[i][j];
                float d = fmaf(f * ce, sz[i], eq);
                bool p1 = d < m1[i], p2 = d < m2[i], p3 = d < m3[i];
                i2[i] = p1 ? i1[i] : (p2 ? code : i2[i]);
                i1[i] = p1 ? code : i1[i];
                m3[i] = p3 ? (p2 ? m2[i] : d) : m3[i];
                m2[i] = p2 ? (p1 ? m1[i] : d) : m2[i];
                m1[i] = p1 ? d : m1[i];
            }
        }
        __syncthreads();   // stage c&1 fully read before it can be overwritten
    }
    float* rm1 = (float*)(sm + SM_MRG);
    float* rm2 = rm1 + 2048; float* rm3 = rm2 + 2048;
    int* ri1 = (int*)(rm3 + 2048); int* ri2 = ri1 + 2048;
    #pragma unroll
    for (int i = 0; i < 8; i++) {
        int s = (ty * 8 + i) * 16 + tx;
        rm1[s] = m1[i]; rm2[s] = m2[i]; rm3[s] = m3[i]; ri1[s] = i1[i]; ri2[s] = i2[i];
    }
    __syncthreads();
    if (t < 128) {
        float v1 = FINF, v2 = FINF, v3 = FINF; int a1 = 0x7fffffff, a2 = 0x7fffffff;
        for (int e = 0; e < 16; e++) {
            int s = t * 16 + e;
            float d; int cdx;
            d = rm1[s]; cdx = ri1[s];
            if (d < v1 || (d == v1 && cdx < a1)) { v3 = v2; v2 = v1; a2 = a1; v1 = d; a1 = cdx; }
            else if (d < v2 || (d == v2 && cdx < a2)) { v3 = v2; v2 = d; a2 = cdx; }
            else if (d < v3) v3 = d;
            d = rm2[s]; cdx = ri2[s];
            if (d < v1 || (d == v1 && cdx < a1)) { v3 = v2; v2 = v1; a2 = a1; v1 = d; a1 = cdx; }
            else if (d < v2 || (d == v2 && cdx < a2)) { v3 = v2; v2 = d; a2 = cdx; }
            else if (d < v3) v3 = d;
            d = rm3[s];
            if (d < v3) v3 = d;
        }
        int row = tile * 128 + t;
        g_idx[row] = a1;
        if (v2 - v1 <= MARGIN) {
            if (v3 - v1 > MARGIN) {
                int p = atomicAdd(&g_duel_n, 1); g_duel[p] = row; g_duelc[p] = make_int2(a1, a2);
            } else {
                int p = atomicAdd(&g_full_n, 1); g_full[p] = row;
            }
        }
    }
}

// ---------------- exact resolution ----------------
__global__ void duel_kernel(const float* __restrict__ z, const float* __restrict__ cb) {
    int n = g_duel_n;
    for (int a = blockIdx.x * blockDim.x + threadIdx.x; a < n; a += gridDim.x * blockDim.x) {
        int row = g_duel[a]; int2 cc = g_duelc[a];
        const float* zr = z + (size_t)row * DDIM;
        const float* ea = cb + (size_t)cc.x * DDIM;
        const float* eb = cb + (size_t)cc.y * DDIM;
        float ca = 0.f, cv = 0.f, zq = 0.f;
        #pragma unroll 8
        for (int d = 0; d < DDIM; d += 4) {
            float4 zv = __ldg((const float4*)(zr + d));
            float4 av = __ldg((const float4*)(ea + d));
            float4 bv = __ldg((const float4*)(eb + d));
            zq = __fadd_rn(zq, __fmul_rn(zv.x, zv.x)); zq = __fadd_rn(zq, __fmul_rn(zv.y, zv.y));
            zq = __fadd_rn(zq, __fmul_rn(zv.z, zv.z)); zq = __fadd_rn(zq, __fmul_rn(zv.w, zv.w));
            ca = fmaf(zv.x, av.x, ca); cv = fmaf(zv.x, bv.x, cv);
            ca = fmaf(zv.y, av.y, ca); cv = fmaf(zv.y, bv.y, cv);
            ca = fmaf(zv.z, av.z, ca); cv = fmaf(zv.z, bv.z, cv);
            ca = fmaf(zv.w, av.w, ca); cv = fmaf(zv.w, bv.w, cv);
        }
        float da = __fadd_rn(__fsub_rn(zq, __fmul_rn(2.f, ca)), g_esq[cc.x]);
        float db = __fadd_rn(__fsub_rn(zq, __fmul_rn(2.f, cv)), g_esq[cc.y]);
        g_idx[row] = (db < da || (db == da && cc.y < cc.x)) ? cc.y : cc.x;
    }
}

// exact full scan, 8 rows/tile. R11 finding: the un-unrolled dot loop was
// MLP=1 L2-latency-bound (~480k cyc/tile). Full unroll -> chain-bound ~40k.
__global__ __launch_bounds__(256) void fullscan_kernel(const float* __restrict__ z,
                                                       const float* __restrict__ cb) {
    __shared__ float zs[256 * 9];
    __shared__ float szq[8];
    __shared__ float sbv[64]; __shared__ int sbi[64];
    int n = g_full_n;
    int t = threadIdx.x, lane = t & 31, w = t >> 5;
    for (int tb = blockIdx.x; tb * 8 < n; tb += gridDim.x) {
        int cnt = min(8, n - tb * 8);
        __syncthreads();
        for (int r = 0; r < 8; r++) {
            if (r < cnt) zs[t * 9 + r] = z[(size_t)g_full[tb * 8 + r] * DDIM + t];
            else zs[t * 9 + r] = 0.f;
        }
        __syncthreads();
        if (t < 8) {   // exact serial z_sq
            float s = 0.f;
            #pragma unroll 8
            for (int d = 0; d < DDIM; d++) {
                float v = zs[d * 9 + t];
                s = __fadd_rn(s, __fmul_rn(v, v));
            }
            szq[t] = s;
        }
        __syncthreads();
        int r = lane & 7, ks = lane >> 3;
        float zq = szq[r];
        float bv = FINF; int bi = 0x7fffffff;
        for (int j = 0; j < 32; j++) {
            int k = j * 32 + w * 4 + ks;
            const float* er = cb + (size_t)k * DDIM;
            float c = 0.f;
            #pragma unroll
            for (int d = 0; d < DDIM; d += 4) {
                float4 ev = __ldg((const float4*)(er + d));
                c = fmaf(zs[(d + 0) * 9 + r], ev.x, c);
                c = fmaf(zs[(d + 1) * 9 + r], ev.y, c);
                c = fmaf(zs[(d + 2) * 9 + r], ev.z, c);
                c = fmaf(zs[(d + 3) * 9 + r], ev.w, c);
            }
            float dist = __fadd_rn(__fsub_rn(zq, __fmul_rn(2.f, c)), __ldg(&g_esq[k]));
            if (dist < bv || (dist == bv && k < bi)) { bv = dist; bi = k; }
        }
        #pragma unroll
        for (int msk = 8; msk <= 16; msk <<= 1) {
            float ov = __shfl_xor_sync(0xffffffffu, bv, msk);
            int   oi = __shfl_xor_sync(0xffffffffu, bi, msk);
            if (ov < bv || (ov == bv && oi < bi)) { bv = ov; bi = oi; }
        }
        if (ks == 0) { sbv[w * 8 + r] = bv; sbi[w * 8 + r] = bi; }
        __syncthreads();
        if (t < cnt) {
            float fv = sbv[t]; int fi = sbi[t];
            #pragma unroll
            for (int ww = 1; ww < 8; ww++) {
                float ov = sbv[ww * 8 + t]; int oi = sbi[ww * 8 + t];
                if (ov < fv || (ov == fv && oi < fi)) { fv = ov; fi = oi; }
            }
            g_idx[g_full[tb * 8 + t]] = fi;
        }
    }
}

// ---------------- gather + loss ----------------
__global__ __launch_bounds__(256) void gather_kernel(const float* __restrict__ z,
                                                     const float* __restrict__ cb,
                                                     float* __restrict__ out) {
    __shared__ int sidx[128]; __shared__ float red[256];
    int t = threadIdx.x, rowbase = blockIdx.x * 128;
    if (t < 128) sidx[t] = g_idx[rowbase + t];
    __syncthreads();
    float lsum = 0.f;
    for (int r = 0; r < 128; r++) {
        int idx = sidx[r];
        float zq = cb[(size_t)idx * DDIM + t];
        float ze = z[(size_t)(rowbase + r) * DDIM + t];
        out[(size_t)(rowbase + r) * DDIM + t] = zq;
        float df = zq - ze; lsum = fmaf(df, df, lsum);
    }
    red[t] = lsum; __syncthreads();
    for (int s = 128; s; s >>= 1) { if (t < s) red[t] += red[t + s]; __syncthreads(); }
    if (t == 0) g_partial[blockIdx.x] = red[0];
}

__global__ void finalize_kernel(float* __restrict__ out, int out_size) {
    __shared__ float red[512];
    int t = threadIdx.x;
    red[t] = g_partial[t];
    __syncthreads();
    for (int s = 256; s; s >>= 1) { if (t < s) red[t] += red[t + s]; __syncthreads(); }
    float loss = red[0] / (float)((long long)NROWS * DDIM);
    const long long base = (long long)NROWS * DDIM;
    for (long long i = base + t; i < (long long)out_size; i += blockDim.x) out[i] = loss;
}

extern "C" void kernel_launch(void* const* d_in, const int* in_sizes, int n_in,
                              void* d_out, int out_size) {
    const float* z  = (const float*)d_in[0];
    const float* cb = (const float*)d_in[1];
    if (n_in >= 2 && in_sizes[0] == KCODES * DDIM && in_sizes[1] == NROWS * DDIM) {
        z = (const float*)d_in[1]; cb = (const float*)d_in[0];
    }
    float* out = (float*)d_out;
    cudaFuncSetAttribute(vq_kernel, cudaFuncAttributeMaxDynamicSharedMemorySize, SMEM_VQ);

    zquant_kernel<<<8192, 256>>>(z);
    cbscale_kernel<<<4, 256>>>(cb);
    cbquant_kernel<<<4, 256>>>(cb);
    vq_kernel<<<NTILES, 256, SMEM_VQ>>>();
    duel_kernel<<<256, 256>>>(z, cb);
    fullscan_kernel<<<592, 256>>>(z, cb);
    gather_kernel<<<512, 256>>>(z, cb, out);
    finalize_kernel<<<1, 512>>>(out, out_size);
}

// round 13
// speedup vs baseline: 16.6086x; 1.6600x over previous
#include <cuda_runtime.h>
#include <cstdint>

#define NROWS  65536
#define DDIM   256
#define KCODES 1024
#define NTILES 512
#define MARGIN 2e-3f
#define FINF   3.4e38f
#define RING   28

typedef unsigned int u32; typedef unsigned long long u64;

__device__ __align__(16) u32 gAq[NTILES * 64 * 128];  // [tile][k4][row] int8x4
__device__ __align__(16) u32 gBq[16 * 64 * 64];       // [chunk64][k4][code] int8x4
__device__ float g_esq[KCODES];
__device__ float g_ce[KCODES];        // -2 * s_e
__device__ float g_zs[NROWS];         // s_z per row
__device__ int   g_idx[NROWS];
__device__ int   g_amb[NROWS];
__device__ float g_ambv[NROWS];
__device__ u64   g_cand[(size_t)NROWS * RING];
__device__ int   g_ccnt[NROWS];
__device__ int   g_amb_n;
__device__ float g_partial[NTILES];

__device__ __forceinline__ u32 smem_u32(const void* p) {
    u32 a; asm("{ .reg .u64 t; cvta.to.shared.u64 t, %1; cvt.u32.u64 %0, t; }" : "=r"(a) : "l"(p));
    return a;
}
__device__ __forceinline__ void cpasync16(u32 dst, const void* src) {
    u64 g = (u64)__cvta_generic_to_global(src);
    asm volatile("cp.async.cg.shared.global [%0], [%1], 16;" :: "r"(dst), "l"(g) : "memory");
}
__device__ __forceinline__ int dp4a(u32 a, u32 b, int c) {
    int r;
    asm("dp4a.s32.s32 %0, %1, %2, %3;" : "=r"(r) : "r"(a), "r"(b), "r"(c));
    return r;
}
__device__ __forceinline__ u32 q4(float a, float b, float c, float d, float inv) {
    int qa = max(-127, min(127, __float2int_rn(a * inv)));
    int qb = max(-127, min(127, __float2int_rn(b * inv)));
    int qc = max(-127, min(127, __float2int_rn(c * inv)));
    int qd = max(-127, min(127, __float2int_rn(d * inv)));
    return (u32)(qa & 255) | ((u32)(qb & 255) << 8) | ((u32)(qc & 255) << 16) | ((u32)(qd & 255) << 24);
}
// monotone float<->u32 encoding (for atomicMin on floats incl. negatives)
__device__ __forceinline__ u32 fenc(float f) {
    u32 b = __float_as_uint(f);
    return (b & 0x80000000u) ? ~b : (b | 0x80000000u);
}
__device__ __forceinline__ float fdec(u32 e) {
    u32 b = (e & 0x80000000u) ? (e & 0x7fffffffu) : ~e;
    return __uint_as_float(b);
}

// ---------------- prep ----------------
__global__ void zquant_kernel(const float* __restrict__ z) {
    int w = (blockIdx.x * blockDim.x + threadIdx.x) >> 5, lane = threadIdx.x & 31;
    const float* row = z + (size_t)w * DDIM;
    float4 v0 = __ldg((const float4*)(row + lane * 8));
    float4 v1 = __ldg((const float4*)(row + lane * 8 + 4));
    float mx = fmaxf(fmaxf(fmaxf(fabsf(v0.x), fabsf(v0.y)), fmaxf(fabsf(v0.z), fabsf(v0.w))),
                     fmaxf(fmaxf(fabsf(v1.x), fabsf(v1.y)), fmaxf(fabsf(v1.z), fabsf(v1.w))));
    #pragma unroll
    for (int m = 16; m; m >>= 1) mx = fmaxf(mx, __shfl_xor_sync(0xffffffffu, mx, m));
    mx = fmaxf(mx, 1e-30f);
    float inv = 127.0f / mx;
    if (lane == 0) { g_zs[w] = mx / 127.0f; g_ccnt[w] = 0; }
    u32 p0 = q4(v0.x, v0.y, v0.z, v0.w, inv);
    u32 p1 = q4(v1.x, v1.y, v1.z, v1.w, inv);
    int tile = w >> 7, rloc = w & 127;
    gAq[(tile * 64 + lane * 2 + 0) * 128 + rloc] = p0;
    gAq[(tile * 64 + lane * 2 + 1) * 128 + rloc] = p1;
}

__global__ void cbscale_kernel(const float* __restrict__ cb) {
    int k = blockIdx.x * blockDim.x + threadIdx.x;
    if (k == 0) g_amb_n = 0;
    if (k >= KCODES) return;
    const float* row = cb + (size_t)k * DDIM;
    float s = 0.f, mx = 1e-30f;
    #pragma unroll 8
    for (int d = 0; d < DDIM; d += 4) {
        float4 v = *(const float4*)&row[d];
        s = __fadd_rn(s, __fmul_rn(v.x, v.x)); s = __fadd_rn(s, __fmul_rn(v.y, v.y));
        s = __fadd_rn(s, __fmul_rn(v.z, v.z)); s = __fadd_rn(s, __fmul_rn(v.w, v.w));
        mx = fmaxf(mx, fmaxf(fmaxf(fabsf(v.x), fabsf(v.y)), fmaxf(fabsf(v.z), fabsf(v.w))));
    }
    g_esq[k] = s;
    g_ce[k] = -2.0f * (mx / 127.0f);
}

__global__ void cbquant_kernel(const float* __restrict__ cb) {
    int k = blockIdx.x * blockDim.x + threadIdx.x;
    if (k >= KCODES) return;
    const float* row = cb + (size_t)k * DDIM;
    float inv = 1.0f / (-0.5f * g_ce[k]);
    int chunk = k >> 6, kloc = k & 63;
    #pragma unroll 8
    for (int d = 0; d < DDIM; d += 4) {
        float4 v = *(const float4*)&row[d];
        gBq[(chunk * 64 + (d >> 2)) * 64 + kloc] = q4(v.x, v.y, v.z, v.w, inv);
    }
}

// ---------------- main dp4a GEMM + candidate ring ----------------
#define SM_A     0
#define SM_B(s)  (32768 + (s) * 16384)
#define SM_RMIN  (32768 + 32768)        // 128 u32
#define SM_MRG   0                      // overlay after compute
#define SMEM_VQ  (65536 + 512)

__global__ __launch_bounds__(256, 2) void vq_kernel() {
    extern __shared__ unsigned char sm[];
    u32 sb = smem_u32(sm);
    u32* rowsmin = (u32*)(sm + SM_RMIN);
    const int t = threadIdx.x, tx = t & 15, ty = t >> 4;
    const int tile = blockIdx.x;

    for (int i = t; i < 2048; i += 256)
        cpasync16(sb + SM_A + i * 16, (const char*)gAq + (size_t)tile * 32768 + i * 16);
    for (int i = t; i < 1024; i += 256)
        cpasync16(sb + SM_B(0) + i * 16, (const char*)gBq + i * 16);
    asm volatile("cp.async.commit_group;" ::: "memory");

    if (t < 128) rowsmin[t] = 0xFFFFFFFFu;

    float sz[8];
    #pragma unroll
    for (int i = 0; i < 8; i++) sz[i] = g_zs[tile * 128 + ty * 8 + i];
    float m1[8], m2[8]; int i1[8];
    #pragma unroll
    for (int i = 0; i < 8; i++) { m1[i] = FINF; m2[i] = FINF; i1[i] = 0x7fffffff; }

    for (int c = 0; c < 16; c++) {
        if (c < 15) {
            u32 dst = sb + SM_B((c + 1) & 1);
            const char* src = (const char*)gBq + (size_t)(c + 1) * 16384;
            for (int i = t; i < 1024; i += 256) cpasync16(dst + i * 16, src + i * 16);
            asm volatile("cp.async.commit_group;" ::: "memory");
            asm volatile("cp.async.wait_group 1;" ::: "memory");
        } else {
            asm volatile("cp.async.wait_group 0;" ::: "memory");
        }
        __syncthreads();

        int acc[8][4];
        #pragma unroll
        for (int i = 0; i < 8; i++)
            #pragma unroll
            for (int j = 0; j < 4; j++) acc[i][j] = 0;

        u32 bst = sb + SM_B(c & 1);
        #pragma unroll 4
        for (int r = 0; r < 32; r++) {
            int k4 = r * 2;
            uint4 a0 = *(const uint4*)(sm + SM_A + k4 * 512 + ty * 32);
            uint4 a1 = *(const uint4*)(sm + SM_A + k4 * 512 + ty * 32 + 16);
            uint4 a2 = *(const uint4*)(sm + SM_A + (k4 + 1) * 512 + ty * 32);
            uint4 a3 = *(const uint4*)(sm + SM_A + (k4 + 1) * 512 + ty * 32 + 16);
            u32 b0[4], b1[4];
            #pragma unroll
            for (int j = 0; j < 4; j++) {
                b0[j] = *(const u32*)((const unsigned char*)sm + (bst - sb) + k4 * 256 + (tx + j * 16) * 4);
                b1[j] = *(const u32*)((const unsigned char*)sm + (bst - sb) + (k4 + 1) * 256 + (tx + j * 16) * 4);
            }
            u32 ar0[8] = {a0.x, a0.y, a0.z, a0.w, a1.x, a1.y, a1.z, a1.w};
            u32 ar1[8] = {a2.x, a2.y, a2.z, a2.w, a3.x, a3.y, a3.z, a3.w};
            #pragma unroll
            for (int j = 0; j < 4; j++)
                #pragma unroll
                for (int i = 0; i < 8; i++) {
                    acc[i][j] = dp4a(ar0[i], b0[j], acc[i][j]);
                    acc[i][j] = dp4a(ar1[i], b1[j], acc[i][j]);
                }
        }
        // pass 1: thread-local top-2 + publish row min
        float dreg[8][4];
        float m1_prev[8];
        #pragma unroll
        for (int i = 0; i < 8; i++) m1_prev[i] = m1[i];
        #pragma unroll
        for (int j = 0; j < 4; j++) {
            int code = c * 64 + tx + j * 16;
            float ce = __ldg(&g_ce[code]);
            float eq = __ldg(&g_esq[code]);
            #pragma unroll
            for (int i = 0; i < 8; i++) {
                float d = fmaf((float)acc[i][j] * ce, sz[i], eq);
                dreg[i][j] = d;
                bool p1 = d < m1[i], p2 = d < m2[i];
                i1[i] = p1 ? code : i1[i];
                m2[i] = p2 ? (p1 ? m1[i] : d) : m2[i];
                m1[i] = p1 ? d : m1[i];
            }
        }
        #pragma unroll
        for (int i = 0; i < 8; i++)
            if (m1[i] < m1_prev[i]) atomicMin(&rowsmin[ty * 8 + i], fenc(m1[i]));
        __syncthreads();
        // pass 2: append candidates within margin of current row min
        #pragma unroll
        for (int i = 0; i < 8; i++) {
            float thr = fdec(rowsmin[ty * 8 + i]) + MARGIN;
            int row = tile * 128 + ty * 8 + i;
            #pragma unroll
            for (int j = 0; j < 4; j++) {
                if (dreg[i][j] <= thr) {
                    int code = c * 64 + tx + j * 16;
                    int pos = atomicAdd(&g_ccnt[row], 1);
                    if (pos < RING)
                        g_cand[(size_t)row * RING + pos] =
                            ((u64)__float_as_uint(dreg[i][j]) << 32) | (u32)code;
                }
            }
        }
        __syncthreads();   // stage c&1 fully read + rowsmin stable before next chunk
    }
    float* rm1 = (float*)(sm + SM_MRG);
    float* rm2 = rm1 + 2048;
    int*   ri1 = (int*)(rm2 + 2048);
    #pragma unroll
    for (int i = 0; i < 8; i++) {
        int s = (ty * 8 + i) * 16 + tx;
        rm1[s] = m1[i]; rm2[s] = m2[i]; ri1[s] = i1[i];
    }
    __syncthreads();
    if (t < 128) {
        float v1 = FINF, v2 = FINF; int a1 = 0x7fffffff;
        for (int e = 0; e < 16; e++) {
            int s = t * 16 + e;
            float d = rm1[s]; int cdx = ri1[s];
            if (d < v1 || (d == v1 && cdx < a1)) { v2 = v1; v1 = d; a1 = cdx; }
            else if (d < v2) v2 = d;
            d = rm2[s];
            if (d < v2) v2 = d;
        }
        int row = tile * 128 + t;
        g_idx[row] = a1;
        if (v2 - v1 <= MARGIN) {
            int p = atomicAdd(&g_amb_n, 1);
            g_amb[p] = row; g_ambv[p] = v1;
        }
    }
}

// ---------------- exact resolution: warp per ambiguous row ----------------
__global__ __launch_bounds__(256) void resolve_kernel(const float* __restrict__ z,
                                                      const float* __restrict__ cb) {
    int n = g_amb_n;
    int wid = (blockIdx.x * blockDim.x + threadIdx.x) >> 5, lane = threadIdx.x & 31;
    int nw = (gridDim.x * blockDim.x) >> 5;
    for (int a = wid; a < n; a += nw) {
        int row = g_amb[a];
        float v1 = g_ambv[a];
        int cnt = g_ccnt[row];
        const float* zr = z + (size_t)row * DDIM;
        float bestv = FINF; int besti = 0x7fffffff;
        if (cnt <= RING) {
            // candidate mode: lane <- ring entry, filter to final margin window
            int code = 0x7fffffff; bool act = false;
            if (lane < cnt) {
                u64 e = g_cand[(size_t)row * RING + lane];
                float da = __uint_as_float((u32)(e >> 32));
                code = (int)(u32)e;
                act = (da <= v1 + MARGIN);
            }
            if (act) {
                const float* er = cb + (size_t)code * DDIM;
                float cr = 0.f, zq = 0.f;
                #pragma unroll 8
                for (int d = 0; d < DDIM; d += 4) {
                    float4 zv = __ldg((const float4*)(zr + d));
                    float4 ev = __ldg((const float4*)(er + d));
                    zq = __fadd_rn(zq, __fmul_rn(zv.x, zv.x)); zq = __fadd_rn(zq, __fmul_rn(zv.y, zv.y));
                    zq = __fadd_rn(zq, __fmul_rn(zv.z, zv.z)); zq = __fadd_rn(zq, __fmul_rn(zv.w, zv.w));
                    cr = fmaf(zv.x, ev.x, cr); cr = fmaf(zv.y, ev.y, cr);
                    cr = fmaf(zv.z, ev.z, cr); cr = fmaf(zv.w, ev.w, cr);
                }
                bestv = __fadd_rn(__fsub_rn(zq, __fmul_rn(2.f, cr)), __ldg(&g_esq[code]));
                besti = code;
            }
        } else {
            // ring overflow (rare): exact lane-strided full scan
            float zq = 0.f;
            #pragma unroll 8
            for (int d = 0; d < DDIM; d += 4) {
                float4 zv = __ldg((const float4*)(zr + d));
                zq = __fadd_rn(zq, __fmul_rn(zv.x, zv.x)); zq = __fadd_rn(zq, __fmul_rn(zv.y, zv.y));
                zq = __fadd_rn(zq, __fmul_rn(zv.z, zv.z)); zq = __fadd_rn(zq, __fmul_rn(zv.w, zv.w));
            }
            for (int k = lane; k < KCODES; k += 32) {
                const float* er = cb + (size_t)k * DDIM;
                float cr = 0.f;
                #pragma unroll 8
                for (int d = 0; d < DDIM; d += 4) {
                    float4 zv = __ldg((const float4*)(zr + d));
                    float4 ev = __ldg((const float4*)(er + d));
                    cr = fmaf(zv.x, ev.x, cr); cr = fmaf(zv.y, ev.y, cr);
                    cr = fmaf(zv.z, ev.z, cr); cr = fmaf(zv.w, ev.w, cr);
                }
                float dist = __fadd_rn(__fsub_rn(zq, __fmul_rn(2.f, cr)), __ldg(&g_esq[k]));
                if (dist < bestv) { bestv = dist; besti = k; }   // ascending k => lowest idx kept
            }
        }
        // warp argmin, lowest-index tiebreak
        #pragma unroll
        for (int off = 16; off; off >>= 1) {
            float ov = __shfl_down_sync(0xffffffffu, bestv, off);
            int   oi = __shfl_down_sync(0xffffffffu, besti, off);
            if (ov < bestv || (ov == bestv && oi < besti)) { bestv = ov; besti = oi; }
        }
        if (lane == 0) g_idx[row] = besti;
    }
}

// ---------------- gather + loss ----------------
__global__ __launch_bounds__(256) void gather_kernel(const float* __restrict__ z,
                                                     const float* __restrict__ cb,
                                                     float* __restrict__ out) {
    __shared__ int sidx[128]; __shared__ float red[256];
    int t = threadIdx.x, rowbase = blockIdx.x * 128;
    if (t < 128) sidx[t] = g_idx[rowbase + t];
    __syncthreads();
    float lsum = 0.f;
    #pragma unroll 4
    for (int r = 0; r < 128; r++) {
        int idx = sidx[r];
        float zq = cb[(size_t)idx * DDIM + t];
        float ze = z[(size_t)(rowbase + r) * DDIM + t];
        out[(size_t)(rowbase + r) * DDIM + t] = zq;
        float df = zq - ze; lsum = fmaf(df, df, lsum);
    }
    red[t] = lsum; __syncthreads();
    for (int s = 128; s; s >>= 1) { if (t < s) red[t] += red[t + s]; __syncthreads(); }
    if (t == 0) g_partial[blockIdx.x] = red[0];
}

__global__ void finalize_kernel(float* __restrict__ out, int out_size) {
    __shared__ float red[512];
    int t = threadIdx.x;
    red[t] = g_partial[t];
    __syncthreads();
    for (int s = 256; s; s >>= 1) { if (t < s) red[t] += red[t + s]; __syncthreads(); }
    float loss = red[0] / (float)((long long)NROWS * DDIM);
    const long long base = (long long)NROWS * DDIM;
    for (long long i = base + t; i < (long long)out_size; i += blockDim.x) out[i] = loss;
}

extern "C" void kernel_launch(void* const* d_in, const int* in_sizes, int n_in,
                              void* d_out, int out_size) {
    const float* z  = (const float*)d_in[0];
    const float* cb = (const float*)d_in[1];
    if (n_in >= 2 && in_sizes[0] == KCODES * DDIM && in_sizes[1] == NROWS * DDIM) {
        z = (const float*)d_in[1]; cb = (const float*)d_in[0];
    }
    float* out = (float*)d_out;
    cudaFuncSetAttribute(vq_kernel, cudaFuncAttributeMaxDynamicSharedMemorySize, SMEM_VQ);

    zquant_kernel<<<8192, 256>>>(z);
    cbscale_kernel<<<4, 256>>>(cb);
    cbquant_kernel<<<4, 256>>>(cb);
    vq_kernel<<<NTILES, 256, SMEM_VQ>>>();
    resolve_kernel<<<256, 256>>>(z, cb);
    gather_kernel<<<512, 256>>>(z, cb, out);
    finalize_kernel<<<1, 512>>>(out, out_size);
}

// round 14
// speedup vs baseline: 17.6045x; 1.0600x over previous
#include <cuda_runtime.h>
#include <cstdint>

#define NROWS  65536
#define DDIM   256
#define KCODES 1024
#define NT64   1024          // tiles of 64 rows
#define MARGIN 2e-3f
#define FINF   3.4e38f
#define RING   28

typedef unsigned int u32; typedef unsigned long long u64;

__device__ __align__(16) u32 gAq[NT64 * 64 * 64];     // [tile64][k4][row] int8x4
__device__ __align__(16) u32 gBq[16 * 64 * 64];       // [chunk64][k4][code] int8x4
__device__ float g_esq[KCODES];
__device__ float g_ce[KCODES];        // -2 * s_e
__device__ float g_zs[NROWS];         // s_z per row
__device__ int   g_idx[NROWS];
__device__ int   g_amb[NROWS];
__device__ float g_ambv[NROWS];
__device__ u64   g_cand[(size_t)NROWS * RING];
__device__ int   g_ccnt[NROWS];
__device__ int   g_amb_n;
__device__ int   g_tilectr;
__device__ float g_partial[512];

__device__ __forceinline__ u32 smem_u32(const void* p) {
    u32 a; asm("{ .reg .u64 t; cvta.to.shared.u64 t, %1; cvt.u32.u64 %0, t; }" : "=r"(a) : "l"(p));
    return a;
}
__device__ __forceinline__ void cpasync16(u32 dst, const void* src) {
    u64 g = (u64)__cvta_generic_to_global(src);
    asm volatile("cp.async.cg.shared.global [%0], [%1], 16;" :: "r"(dst), "l"(g) : "memory");
}
__device__ __forceinline__ int dp4a(u32 a, u32 b, int c) {
    int r;
    asm("dp4a.s32.s32 %0, %1, %2, %3;" : "=r"(r) : "r"(a), "r"(b), "r"(c));
    return r;
}
__device__ __forceinline__ u32 q4(float a, float b, float c, float d, float inv) {
    int qa = max(-127, min(127, __float2int_rn(a * inv)));
    int qb = max(-127, min(127, __float2int_rn(b * inv)));
    int qc = max(-127, min(127, __float2int_rn(c * inv)));
    int qd = max(-127, min(127, __float2int_rn(d * inv)));
    return (u32)(qa & 255) | ((u32)(qb & 255) << 8) | ((u32)(qc & 255) << 16) | ((u32)(qd & 255) << 24);
}
__device__ __forceinline__ u32 fenc(float f) {
    u32 b = __float_as_uint(f);
    return (b & 0x80000000u) ? ~b : (b | 0x80000000u);
}
__device__ __forceinline__ float fdec(u32 e) {
    u32 b = (e & 0x80000000u) ? (e & 0x7fffffffu) : ~e;
    return __uint_as_float(b);
}

// ---------------- prep ----------------
__global__ void zquant_kernel(const float* __restrict__ z) {
    int w = (blockIdx.x * blockDim.x + threadIdx.x) >> 5, lane = threadIdx.x & 31;
    const float* row = z + (size_t)w * DDIM;
    float4 v0 = __ldg((const float4*)(row + lane * 8));
    float4 v1 = __ldg((const float4*)(row + lane * 8 + 4));
    float mx = fmaxf(fmaxf(fmaxf(fabsf(v0.x), fabsf(v0.y)), fmaxf(fabsf(v0.z), fabsf(v0.w))),
                     fmaxf(fmaxf(fabsf(v1.x), fabsf(v1.y)), fmaxf(fabsf(v1.z), fabsf(v1.w))));
    #pragma unroll
    for (int m = 16; m; m >>= 1) mx = fmaxf(mx, __shfl_xor_sync(0xffffffffu, mx, m));
    mx = fmaxf(mx, 1e-30f);
    float inv = 127.0f / mx;
    if (lane == 0) { g_zs[w] = mx / 127.0f; g_ccnt[w] = 0; }
    u32 p0 = q4(v0.x, v0.y, v0.z, v0.w, inv);
    u32 p1 = q4(v1.x, v1.y, v1.z, v1.w, inv);
    int tile = w >> 6, rloc = w & 63;
    gAq[((size_t)tile * 64 + lane * 2 + 0) * 64 + rloc] = p0;
    gAq[((size_t)tile * 64 + lane * 2 + 1) * 64 + rloc] = p1;
}

__global__ void cbscale_kernel(const float* __restrict__ cb) {
    int k = blockIdx.x * blockDim.x + threadIdx.x;
    if (k == 0) { g_amb_n = 0; g_tilectr = 0; }
    if (k >= KCODES) return;
    const float* row = cb + (size_t)k * DDIM;
    float s = 0.f, mx = 1e-30f;
    #pragma unroll 8
    for (int d = 0; d < DDIM; d += 4) {
        float4 v = *(const float4*)&row[d];
        s = __fadd_rn(s, __fmul_rn(v.x, v.x)); s = __fadd_rn(s, __fmul_rn(v.y, v.y));
        s = __fadd_rn(s, __fmul_rn(v.z, v.z)); s = __fadd_rn(s, __fmul_rn(v.w, v.w));
        mx = fmaxf(mx, fmaxf(fmaxf(fabsf(v.x), fabsf(v.y)), fmaxf(fabsf(v.z), fabsf(v.w))));
    }
    g_esq[k] = s;
    g_ce[k] = -2.0f * (mx / 127.0f);
}

__global__ void cbquant_kernel(const float* __restrict__ cb) {
    int k = blockIdx.x * blockDim.x + threadIdx.x;
    if (k >= KCODES) return;
    const float* row = cb + (size_t)k * DDIM;
    float inv = 1.0f / (-0.5f * g_ce[k]);
    int chunk = k >> 6, kloc = k & 63;
    #pragma unroll 8
    for (int d = 0; d < DDIM; d += 4) {
        float4 v = *(const float4*)&row[d];
        gBq[(chunk * 64 + (d >> 2)) * 64 + kloc] = q4(v.x, v.y, v.z, v.w, inv);
    }
}

// ---------------- main dp4a GEMM + candidate ring (persistent, M=64) -------
#define SM_A     0                      // 64 k4 x 64 rows x 4B = 16384
#define SM_B(s)  (16384 + (s) * 16384)  // 2 stages
#define SM_RMIN  49152                  // 64 u32
#define SM_TILE  49408                  // 1 int
#define SM_MRG   0                      // overlay after compute (12KB < 16KB)
#define SMEM_VQ  49664

__global__ __launch_bounds__(256, 3) void vq_kernel() {
    extern __shared__ unsigned char sm[];
    u32 sb = smem_u32(sm);
    u32* rowsmin = (u32*)(sm + SM_RMIN);
    int* tilebuf = (int*)(sm + SM_TILE);
    const int t = threadIdx.x, tx = t & 15, ty = t >> 4;

    for (;;) {
        if (t == 0) *tilebuf = atomicAdd(&g_tilectr, 1);
        __syncthreads();                    // publishes tile; also guards SM_A overlay reuse
        const int tile = *tilebuf;
        if (tile >= NT64) break;

        // A (16KB) + B chunk 0 (16KB) in group G0
        for (int i = t; i < 1024; i += 256)
            cpasync16(sb + SM_A + i * 16, (const char*)gAq + (size_t)tile * 16384 + i * 16);
        for (int i = t; i < 1024; i += 256)
            cpasync16(sb + SM_B(0) + i * 16, (const char*)gBq + i * 16);
        asm volatile("cp.async.commit_group;" ::: "memory");

        if (t < 64) rowsmin[t] = 0xFFFFFFFFu;

        float sz[4];
        #pragma unroll
        for (int i = 0; i < 4; i++) sz[i] = g_zs[tile * 64 + ty * 4 + i];
        float m1[4], m2[4]; int i1[4];
        #pragma unroll
        for (int i = 0; i < 4; i++) { m1[i] = FINF; m2[i] = FINF; i1[i] = 0x7fffffff; }

        for (int c = 0; c < 16; c++) {
            if (c < 15) {
                u32 dst = sb + SM_B((c + 1) & 1);
                const char* src = (const char*)gBq + (size_t)(c + 1) * 16384;
                for (int i = t; i < 1024; i += 256) cpasync16(dst + i * 16, src + i * 16);
                asm volatile("cp.async.commit_group;" ::: "memory");
                asm volatile("cp.async.wait_group 1;" ::: "memory");
            } else {
                asm volatile("cp.async.wait_group 0;" ::: "memory");
            }
            __syncthreads();                // stage c ready for all threads

            int acc[4][4];
            #pragma unroll
            for (int i = 0; i < 4; i++)
                #pragma unroll
                for (int j = 0; j < 4; j++) acc[i][j] = 0;

            const unsigned char* bst = (const unsigned char*)sm + SM_B(c & 1);
            #pragma unroll 4
            for (int r = 0; r < 32; r++) {
                int k4 = r * 2;
                uint4 a0 = *(const uint4*)(sm + SM_A + k4 * 256 + ty * 16);
                uint4 a1 = *(const uint4*)(sm + SM_A + (k4 + 1) * 256 + ty * 16);
                u32 b0[4], b1[4];
                #pragma unroll
                for (int j = 0; j < 4; j++) {
                    b0[j] = *(const u32*)(bst + k4 * 256 + (tx + j * 16) * 4);
                    b1[j] = *(const u32*)(bst + (k4 + 1) * 256 + (tx + j * 16) * 4);
                }
                u32 ar0[4] = {a0.x, a0.y, a0.z, a0.w};
                u32 ar1[4] = {a1.x, a1.y, a1.z, a1.w};
                #pragma unroll
                for (int j = 0; j < 4; j++)
                    #pragma unroll
                    for (int i = 0; i < 4; i++) {
                        acc[i][j] = dp4a(ar0[i], b0[j], acc[i][j]);
                        acc[i][j] = dp4a(ar1[i], b1[j], acc[i][j]);
                    }
            }
            // pass 1: local top-2 + publish row min
            float dreg[4][4];
            float m1_prev[4];
            #pragma unroll
            for (int i = 0; i < 4; i++) m1_prev[i] = m1[i];
            #pragma unroll
            for (int j = 0; j < 4; j++) {
                int code = c * 64 + tx + j * 16;
                float ce = __ldg(&g_ce[code]);
                float eq = __ldg(&g_esq[code]);
                #pragma unroll
                for (int i = 0; i < 4; i++) {
                    float d = fmaf((float)acc[i][j] * ce, sz[i], eq);
                    dreg[i][j] = d;
                    bool p1 = d < m1[i], p2 = d < m2[i];
                    i1[i] = p1 ? code : i1[i];
                    m2[i] = p2 ? (p1 ? m1[i] : d) : m2[i];
                    m1[i] = p1 ? d : m1[i];
                }
            }
            #pragma unroll
            for (int i = 0; i < 4; i++)
                if (m1[i] < m1_prev[i]) atomicMin(&rowsmin[ty * 4 + i], fenc(m1[i]));
            __syncthreads();                // rowsmin stable; also gates stage reuse
            // pass 2: append candidates within margin of current row min
            #pragma unroll
            for (int i = 0; i < 4; i++) {
                float thr = fdec(rowsmin[ty * 4 + i]) + MARGIN;
                int row = tile * 64 + ty * 4 + i;
                #pragma unroll
                for (int j = 0; j < 4; j++) {
                    if (dreg[i][j] <= thr) {
                        int code = c * 64 + tx + j * 16;
                        int pos = atomicAdd(&g_ccnt[row], 1);
                        if (pos < RING)
                            g_cand[(size_t)row * RING + pos] =
                                ((u64)__float_as_uint(dreg[i][j]) << 32) | (u32)code;
                    }
                }
            }
        }
        __syncthreads();                    // all pass-2 done before SM_A overlay
        float* rm1 = (float*)(sm + SM_MRG);
        float* rm2 = rm1 + 1024;
        int*   ri1 = (int*)(rm2 + 1024);
        #pragma unroll
        for (int i = 0; i < 4; i++) {
            int s = (ty * 4 + i) * 16 + tx;
            rm1[s] = m1[i]; rm2[s] = m2[i]; ri1[s] = i1[i];
        }
        __syncthreads();
        if (t < 64) {
            float v1 = FINF, v2 = FINF; int a1 = 0x7fffffff;
            for (int e = 0; e < 16; e++) {
                int s = t * 16 + e;
                float d = rm1[s]; int cdx = ri1[s];
                if (d < v1 || (d == v1 && cdx < a1)) { v2 = v1; v1 = d; a1 = cdx; }
                else if (d < v2) v2 = d;
                d = rm2[s];
                if (d < v2) v2 = d;
            }
            int row = tile * 64 + t;
            g_idx[row] = a1;
            if (v2 - v1 <= MARGIN) {
                int p = atomicAdd(&g_amb_n, 1);
                g_amb[p] = row; g_ambv[p] = v1;
            }
        }
    }
}

// ---------------- exact resolution: warp per ambiguous row ----------------
__global__ __launch_bounds__(256) void resolve_kernel(const float* __restrict__ z,
                                                      const float* __restrict__ cb) {
    int n = g_amb_n;
    int wid = (blockIdx.x * blockDim.x + threadIdx.x) >> 5, lane = threadIdx.x & 31;
    int nw = (gridDim.x * blockDim.x) >> 5;
    for (int a = wid; a < n; a += nw) {
        int row = g_amb[a];
        float v1 = g_ambv[a];
        int cnt = g_ccnt[row];
        const float* zr = z + (size_t)row * DDIM;
        float bestv = FINF; int besti = 0x7fffffff;
        if (cnt <= RING) {
            int code = 0x7fffffff; bool act = false;
            if (lane < cnt) {
                u64 e = g_cand[(size_t)row * RING + lane];
                float da = __uint_as_float((u32)(e >> 32));
                code = (int)(u32)e;
                act = (da <= v1 + MARGIN);
            }
            if (act) {
                const float* er = cb + (size_t)code * DDIM;
                float cr = 0.f, zq = 0.f;
                #pragma unroll 8
                for (int d = 0; d < DDIM; d += 4) {
                    float4 zv = __ldg((const float4*)(zr + d));
                    float4 ev = __ldg((const float4*)(er + d));
                    zq = __fadd_rn(zq, __fmul_rn(zv.x, zv.x)); zq = __fadd_rn(zq, __fmul_rn(zv.y, zv.y));
                    zq = __fadd_rn(zq, __fmul_rn(zv.z, zv.z)); zq = __fadd_rn(zq, __fmul_rn(zv.w, zv.w));
                    cr = fmaf(zv.x, ev.x, cr); cr = fmaf(zv.y, ev.y, cr);
                    cr = fmaf(zv.z, ev.z, cr); cr = fmaf(zv.w, ev.w, cr);
                }
                bestv = __fadd_rn(__fsub_rn(zq, __fmul_rn(2.f, cr)), __ldg(&g_esq[code]));
                besti = code;
            }
        } else {
            float zq = 0.f;
            #pragma unroll 8
            for (int d = 0; d < DDIM; d += 4) {
                float4 zv = __ldg((const float4*)(zr + d));
                zq = __fadd_rn(zq, __fmul_rn(zv.x, zv.x)); zq = __fadd_rn(zq, __fmul_rn(zv.y, zv.y));
                zq = __fadd_rn(zq, __fmul_rn(zv.z, zv.z)); zq = __fadd_rn(zq, __fmul_rn(zv.w, zv.w));
            }
            for (int k = lane; k < KCODES; k += 32) {
                const float* er = cb + (size_t)k * DDIM;
                float cr = 0.f;
                #pragma unroll 8
                for (int d = 0; d < DDIM; d += 4) {
                    float4 zv = __ldg((const float4*)(zr + d));
                    float4 ev = __ldg((const float4*)(er + d));
                    cr = fmaf(zv.x, ev.x, cr); cr = fmaf(zv.y, ev.y, cr);
                    cr = fmaf(zv.z, ev.z, cr); cr = fmaf(zv.w, ev.w, cr);
                }
                float dist = __fadd_rn(__fsub_rn(zq, __fmul_rn(2.f, cr)), __ldg(&g_esq[k]));
                if (dist < bestv) { bestv = dist; besti = k; }
            }
        }
        #pragma unroll
        for (int off = 16; off; off >>= 1) {
            float ov = __shfl_down_sync(0xffffffffu, bestv, off);
            int   oi = __shfl_down_sync(0xffffffffu, besti, off);
            if (ov < bestv || (ov == bestv && oi < besti)) { bestv = ov; besti = oi; }
        }
        if (lane == 0) g_idx[row] = besti;
    }
}

// ---------------- gather + loss ----------------
__global__ __launch_bounds__(256) void gather_kernel(const float* __restrict__ z,
                                                     const float* __restrict__ cb,
                                                     float* __restrict__ out) {
    __shared__ int sidx[128]; __shared__ float red[256];
    int t = threadIdx.x, rowbase = blockIdx.x * 128;
    if (t < 128) sidx[t] = g_idx[rowbase + t];
    __syncthreads();
    float lsum = 0.f;
    #pragma unroll 4
    for (int r = 0; r < 128; r++) {
        int idx = sidx[r];
        float zq = cb[(size_t)idx * DDIM + t];
        float ze = z[(size_t)(rowbase + r) * DDIM + t];
        out[(size_t)(rowbase + r) * DDIM + t] = zq;
        float df = zq - ze; lsum = fmaf(df, df, lsum);
    }
    red[t] = lsum; __syncthreads();
    for (int s = 128; s; s >>= 1) { if (t < s) red[t] += red[t + s]; __syncthreads(); }
    if (t == 0) g_partial[blockIdx.x] = red[0];
}

__global__ void finalize_kernel(float* __restrict__ out, int out_size) {
    __shared__ float red[512];
    int t = threadIdx.x;
    red[t] = g_partial[t];
    __syncthreads();
    for (int s = 256; s; s >>= 1) { if (t < s) red[t] += red[t + s]; __syncthreads(); }
    float loss = red[0] / (float)((long long)NROWS * DDIM);
    const long long base = (long long)NROWS * DDIM;
    for (long long i = base + t; i < (long long)out_size; i += blockDim.x) out[i] = loss;
}

extern "C" void kernel_launch(void* const* d_in, const int* in_sizes, int n_in,
                              void* d_out, int out_size) {
    const float* z  = (const float*)d_in[0];
    const float* cb = (const float*)d_in[1];
    if (n_in >= 2 && in_sizes[0] == KCODES * DDIM && in_sizes[1] == NROWS * DDIM) {
        z = (const float*)d_in[1]; cb = (const float*)d_in[0];
    }
    float* out = (float*)d_out;
    cudaFuncSetAttribute(vq_kernel, cudaFuncAttributeMaxDynamicSharedMemorySize, SMEM_VQ);

    zquant_kernel<<<8192, 256>>>(z);
    cbscale_kernel<<<4, 256>>>(cb);
    cbquant_kernel<<<4, 256>>>(cb);
    vq_kernel<<<444, 256, SMEM_VQ>>>();
    resolve_kernel<<<256, 256>>>(z, cb);
    gather_kernel<<<512, 256>>>(z, cb, out);
    finalize_kernel<<<1, 512>>>(out, out_size);
}

// round 15
// speedup vs baseline: 19.1092x; 1.0855x over previous
#include <cuda_runtime.h>
#include <cstdint>

#define NROWS  65536
#define DDIM   256
#define KCODES 1024
#define NT64   1024          // tiles of 64 rows
#define MARGIN 2e-3f
#define FINF   3.4e38f
#define RING   28

typedef unsigned int u32; typedef unsigned long long u64;

__device__ __align__(16) u32 gAq[NT64 * 64 * 64];     // [tile64][k4][row] int8x4
__device__ __align__(16) u32 gBq[16 * 64 * 64];       // [chunk64][k4][code] int8x4
__device__ float g_esq[KCODES];
__device__ float g_ce[KCODES];        // -2 * s_e
__device__ float g_zs[NROWS];         // s_z per row
__device__ int   g_idx[NROWS];
__device__ int   g_amb[NROWS];
__device__ float g_ambv[NROWS];
__device__ u64   g_cand[(size_t)NROWS * RING];
__device__ int   g_ccnt[NROWS];
__device__ int   g_amb_n;
__device__ int   g_tilectr;
__device__ float g_partial[512];

__device__ __forceinline__ u32 smem_u32(const void* p) {
    u32 a; asm("{ .reg .u64 t; cvta.to.shared.u64 t, %1; cvt.u32.u64 %0, t; }" : "=r"(a) : "l"(p));
    return a;
}
__device__ __forceinline__ void cpasync16(u32 dst, const void* src) {
    u64 g = (u64)__cvta_generic_to_global(src);
    asm volatile("cp.async.cg.shared.global [%0], [%1], 16;" :: "r"(dst), "l"(g) : "memory");
}
__device__ __forceinline__ int dp4a(u32 a, u32 b, int c) {
    int r;
    asm("dp4a.s32.s32 %0, %1, %2, %3;" : "=r"(r) : "r"(a), "r"(b), "r"(c));
    return r;
}
__device__ __forceinline__ u32 q4(float a, float b, float c, float d, float inv) {
    int qa = max(-127, min(127, __float2int_rn(a * inv)));
    int qb = max(-127, min(127, __float2int_rn(b * inv)));
    int qc = max(-127, min(127, __float2int_rn(c * inv)));
    int qd = max(-127, min(127, __float2int_rn(d * inv)));
    return (u32)(qa & 255) | ((u32)(qb & 255) << 8) | ((u32)(qc & 255) << 16) | ((u32)(qd & 255) << 24);
}

// ---------------- prep ----------------
__global__ void zquant_kernel(const float* __restrict__ z) {
    int w = (blockIdx.x * blockDim.x + threadIdx.x) >> 5, lane = threadIdx.x & 31;
    const float* row = z + (size_t)w * DDIM;
    float4 v0 = __ldg((const float4*)(row + lane * 8));
    float4 v1 = __ldg((const float4*)(row + lane * 8 + 4));
    float mx = fmaxf(fmaxf(fmaxf(fabsf(v0.x), fabsf(v0.y)), fmaxf(fabsf(v0.z), fabsf(v0.w))),
                     fmaxf(fmaxf(fabsf(v1.x), fabsf(v1.y)), fmaxf(fabsf(v1.z), fabsf(v1.w))));
    #pragma unroll
    for (int m = 16; m; m >>= 1) mx = fmaxf(mx, __shfl_xor_sync(0xffffffffu, mx, m));
    mx = fmaxf(mx, 1e-30f);
    float inv = 127.0f / mx;
    if (lane == 0) { g_zs[w] = mx / 127.0f; g_ccnt[w] = 0; }
    u32 p0 = q4(v0.x, v0.y, v0.z, v0.w, inv);
    u32 p1 = q4(v1.x, v1.y, v1.z, v1.w, inv);
    int tile = w >> 6, rloc = w & 63;
    gAq[((size_t)tile * 64 + lane * 2 + 0) * 64 + rloc] = p0;
    gAq[((size_t)tile * 64 + lane * 2 + 1) * 64 + rloc] = p1;
}

// thread per code: EXACT serial esq + scale + quantize; zero counters
__global__ void cbprep_kernel(const float* __restrict__ cb) {
    int k = blockIdx.x * blockDim.x + threadIdx.x;
    if (k == 0) { g_amb_n = 0; g_tilectr = 0; }
    if (k >= KCODES) return;
    const float* row = cb + (size_t)k * DDIM;
    float s = 0.f, mx = 1e-30f;
    #pragma unroll 8
    for (int d = 0; d < DDIM; d += 4) {
        float4 v = *(const float4*)&row[d];
        s = __fadd_rn(s, __fmul_rn(v.x, v.x)); s = __fadd_rn(s, __fmul_rn(v.y, v.y));
        s = __fadd_rn(s, __fmul_rn(v.z, v.z)); s = __fadd_rn(s, __fmul_rn(v.w, v.w));
        mx = fmaxf(mx, fmaxf(fmaxf(fabsf(v.x), fabsf(v.y)), fmaxf(fabsf(v.z), fabsf(v.w))));
    }
    g_esq[k] = s;
    g_ce[k] = -2.0f * (mx / 127.0f);
    float inv = 127.0f / mx;
    int chunk = k >> 6, kloc = k & 63;
    #pragma unroll 8
    for (int d = 0; d < DDIM; d += 4) {
        float4 v = *(const float4*)&row[d];
        gBq[(chunk * 64 + (d >> 2)) * 64 + kloc] = q4(v.x, v.y, v.z, v.w, inv);
    }
}

// ---------------- main dp4a GEMM + candidate ring (persistent, M=64) -------
#define SM_A     0                      // 64 k4 x 64 rows x 4B = 16384
#define SM_B(s)  (16384 + (s) * 16384)  // 2 stages
#define SM_TILE  49152
#define SMEM_VQ  49408

__global__ __launch_bounds__(256, 3) void vq_kernel() {
    extern __shared__ unsigned char sm[];
    u32 sb = smem_u32(sm);
    int* tilebuf = (int*)(sm + SM_TILE);
    const int t = threadIdx.x, tx = t & 15, ty = t >> 4;

    for (;;) {
        if (t == 0) *tilebuf = atomicAdd(&g_tilectr, 1);
        __syncthreads();                    // publish tile; all prior-tile smem reads done
        const int tile = *tilebuf;
        if (tile >= NT64) break;

        // A (16KB) + B chunk 0 (16KB) as group G0
        for (int i = t; i < 1024; i += 256)
            cpasync16(sb + SM_A + i * 16, (const char*)gAq + (size_t)tile * 16384 + i * 16);
        for (int i = t; i < 1024; i += 256)
            cpasync16(sb + SM_B(0) + i * 16, (const char*)gBq + i * 16);
        asm volatile("cp.async.commit_group;" ::: "memory");

        float sz[4];
        #pragma unroll
        for (int i = 0; i < 4; i++) sz[i] = g_zs[tile * 64 + ty * 4 + i];
        float m1[4], m2[4]; int i1[4];
        #pragma unroll
        for (int i = 0; i < 4; i++) { m1[i] = FINF; m2[i] = FINF; i1[i] = 0x7fffffff; }

        for (int c = 0; c < 16; c++) {
            asm volatile("cp.async.wait_group 0;" ::: "memory");
            __syncthreads();                // stage c ready; prior reads of other stage done
            if (c < 15) {                   // prefetch AFTER the sync (overwrite-safe)
                u32 dst = sb + SM_B((c + 1) & 1);
                const char* src = (const char*)gBq + (size_t)(c + 1) * 16384;
                for (int i = t; i < 1024; i += 256) cpasync16(dst + i * 16, src + i * 16);
                asm volatile("cp.async.commit_group;" ::: "memory");
            }

            int acc[4][4];
            #pragma unroll
            for (int i = 0; i < 4; i++)
                #pragma unroll
                for (int j = 0; j < 4; j++) acc[i][j] = 0;

            const unsigned char* bst = (const unsigned char*)sm + SM_B(c & 1);
            #pragma unroll 8
            for (int r = 0; r < 32; r++) {
                int k4 = r * 2;
                uint4 a0 = *(const uint4*)(sm + SM_A + k4 * 256 + ty * 16);
                uint4 a1 = *(const uint4*)(sm + SM_A + (k4 + 1) * 256 + ty * 16);
                uint4 b0 = *(const uint4*)(bst + k4 * 256 + tx * 16);        // codes tx*4..+3
                uint4 b1 = *(const uint4*)(bst + (k4 + 1) * 256 + tx * 16);
                u32 ar0[4] = {a0.x, a0.y, a0.z, a0.w};
                u32 ar1[4] = {a1.x, a1.y, a1.z, a1.w};
                u32 br0[4] = {b0.x, b0.y, b0.z, b0.w};
                u32 br1[4] = {b1.x, b1.y, b1.z, b1.w};
                #pragma unroll
                for (int j = 0; j < 4; j++)
                    #pragma unroll
                    for (int i = 0; i < 4; i++) {
                        acc[i][j] = dp4a(ar0[i], br0[j], acc[i][j]);
                        acc[i][j] = dp4a(ar1[i], br1[j], acc[i][j]);
                    }
            }
            // epilogue: codes c*64 + tx*4 + j  (contiguous per thread)
            float4 ce4 = __ldg((const float4*)&g_ce[c * 64 + tx * 4]);
            float4 eq4 = __ldg((const float4*)&g_esq[c * 64 + tx * 4]);
            float cearr[4] = {ce4.x, ce4.y, ce4.z, ce4.w};
            float eqarr[4] = {eq4.x, eq4.y, eq4.z, eq4.w};
            float dreg[4][4];
            #pragma unroll
            for (int j = 0; j < 4; j++) {
                int code = c * 64 + tx * 4 + j;
                #pragma unroll
                for (int i = 0; i < 4; i++) {
                    float d = fmaf((float)acc[i][j] * cearr[j], sz[i], eqarr[j]);
                    dreg[i][j] = d;
                    bool p1 = d < m1[i], p2 = d < m2[i];
                    i1[i] = p1 ? code : i1[i];
                    m2[i] = p2 ? (p1 ? m1[i] : d) : m2[i];
                    m1[i] = p1 ? d : m1[i];
                }
            }
            // running row-min across the 16 tx lanes (half-warp shfl, no smem)
            #pragma unroll
            for (int i = 0; i < 4; i++) {
                float rm = m1[i];
                #pragma unroll
                for (int msk = 1; msk <= 8; msk <<= 1)
                    rm = fminf(rm, __shfl_xor_sync(0xffffffffu, rm, msk));
                float thr = rm + MARGIN;
                int row = tile * 64 + ty * 4 + i;
                #pragma unroll
                for (int j = 0; j < 4; j++) {
                    if (dreg[i][j] <= thr) {
                        int code = c * 64 + tx * 4 + j;
                        int pos = atomicAdd(&g_ccnt[row], 1);
                        if (pos < RING)
                            g_cand[(size_t)row * RING + pos] =
                                ((u64)__float_as_uint(dreg[i][j]) << 32) | (u32)code;
                    }
                }
            }
        }
        // final per-row top-2 merge across tx lanes via shfl (lexicographic)
        #pragma unroll
        for (int i = 0; i < 4; i++) {
            float v1 = m1[i], v2 = m2[i]; int a1 = i1[i];
            #pragma unroll
            for (int msk = 1; msk <= 8; msk <<= 1) {
                float ov1 = __shfl_xor_sync(0xffffffffu, v1, msk);
                float ov2 = __shfl_xor_sync(0xffffffffu, v2, msk);
                int   oa1 = __shfl_xor_sync(0xffffffffu, a1, msk);
                if (ov1 < v1 || (ov1 == v1 && oa1 < a1)) {
                    v2 = fminf(v1, ov2); v1 = ov1; a1 = oa1;
                } else {
                    v2 = fminf(v2, ov1);
                }
            }
            if (tx == 0) {
                int row = tile * 64 + ty * 4 + i;
                g_idx[row] = a1;
                if (v2 - v1 <= MARGIN) {
                    int p = atomicAdd(&g_amb_n, 1);
                    g_amb[p] = row; g_ambv[p] = v1;
                }
            }
        }
    }
}

// ---------------- exact resolution: warp per ambiguous row ----------------
__global__ __launch_bounds__(256) void resolve_kernel(const float* __restrict__ z,
                                                      const float* __restrict__ cb) {
    int n = g_amb_n;
    int wid = (blockIdx.x * blockDim.x + threadIdx.x) >> 5, lane = threadIdx.x & 31;
    int nw = (gridDim.x * blockDim.x) >> 5;
    for (int a = wid; a < n; a += nw) {
        int row = g_amb[a];
        float v1 = g_ambv[a];
        int cnt = g_ccnt[row];
        const float* zr = z + (size_t)row * DDIM;
        float bestv = FINF; int besti = 0x7fffffff;
        if (cnt <= RING) {
            int code = 0x7fffffff; bool act = false;
            if (lane < cnt) {
                u64 e = g_cand[(size_t)row * RING + lane];
                float da = __uint_as_float((u32)(e >> 32));
                code = (int)(u32)e;
                act = (da <= v1 + MARGIN);
            }
            if (act) {
                const float* er = cb + (size_t)code * DDIM;
                float cr = 0.f, zq = 0.f;
                #pragma unroll 8
                for (int d = 0; d < DDIM; d += 4) {
                    float4 zv = __ldg((const float4*)(zr + d));
                    float4 ev = __ldg((const float4*)(er + d));
                    zq = __fadd_rn(zq, __fmul_rn(zv.x, zv.x)); zq = __fadd_rn(zq, __fmul_rn(zv.y, zv.y));
                    zq = __fadd_rn(zq, __fmul_rn(zv.z, zv.z)); zq = __fadd_rn(zq, __fmul_rn(zv.w, zv.w));
                    cr = fmaf(zv.x, ev.x, cr); cr = fmaf(zv.y, ev.y, cr);
                    cr = fmaf(zv.z, ev.z, cr); cr = fmaf(zv.w, ev.w, cr);
                }
                bestv = __fadd_rn(__fsub_rn(zq, __fmul_rn(2.f, cr)), __ldg(&g_esq[code]));
                besti = code;
            }
        } else {
            float zq = 0.f;
            #pragma unroll 8
            for (int d = 0; d < DDIM; d += 4) {
                float4 zv = __ldg((const float4*)(zr + d));
                zq = __fadd_rn(zq, __fmul_rn(zv.x, zv.x)); zq = __fadd_rn(zq, __fmul_rn(zv.y, zv.y));
                zq = __fadd_rn(zq, __fmul_rn(zv.z, zv.z)); zq = __fadd_rn(zq, __fmul_rn(zv.w, zv.w));
            }
            for (int k = lane; k < KCODES; k += 32) {
                const float* er = cb + (size_t)k * DDIM;
                float cr = 0.f;
                #pragma unroll 8
                for (int d = 0; d < DDIM; d += 4) {
                    float4 zv = __ldg((const float4*)(zr + d));
                    float4 ev = __ldg((const float4*)(er + d));
                    cr = fmaf(zv.x, ev.x, cr); cr = fmaf(zv.y, ev.y, cr);
                    cr = fmaf(zv.z, ev.z, cr); cr = fmaf(zv.w, ev.w, cr);
                }
                float dist = __fadd_rn(__fsub_rn(zq, __fmul_rn(2.f, cr)), __ldg(&g_esq[k]));
                if (dist < bestv) { bestv = dist; besti = k; }
            }
        }
        #pragma unroll
        for (int off = 16; off; off >>= 1) {
            float ov = __shfl_down_sync(0xffffffffu, bestv, off);
            int   oi = __shfl_down_sync(0xffffffffu, besti, off);
            if (ov < bestv || (ov == bestv && oi < besti)) { bestv = ov; besti = oi; }
        }
        if (lane == 0) g_idx[row] = besti;
    }
}

// ---------------- gather + loss ----------------
__global__ __launch_bounds__(256) void gather_kernel(const float* __restrict__ z,
                                                     const float* __restrict__ cb,
                                                     float* __restrict__ out) {
    __shared__ int sidx[128]; __shared__ float red[256];
    int t = threadIdx.x, rowbase = blockIdx.x * 128;
    if (t < 128) sidx[t] = g_idx[rowbase + t];
    __syncthreads();
    float lsum = 0.f;
    #pragma unroll 4
    for (int r = 0; r < 128; r++) {
        int idx = sidx[r];
        float zq = cb[(size_t)idx * DDIM + t];
        float ze = z[(size_t)(rowbase + r) * DDIM + t];
        out[(size_t)(rowbase + r) * DDIM + t] = zq;
        float df = zq - ze; lsum = fmaf(df, df, lsum);
    }
    red[t] = lsum; __syncthreads();
    for (int s = 128; s; s >>= 1) { if (t < s) red[t] += red[t + s]; __syncthreads(); }
    if (t == 0) g_partial[blockIdx.x] = red[0];
}

__global__ void finalize_kernel(float* __restrict__ out, int out_size) {
    __shared__ float red[512];
    int t = threadIdx.x;
    red[t] = g_partial[t];
    __syncthreads();
    for (int s = 256; s; s >>= 1) { if (t < s) red[t] += red[t + s]; __syncthreads(); }
    float loss = red[0] / (float)((long long)NROWS * DDIM);
    const long long base = (long long)NROWS * DDIM;
    for (long long i = base + t; i < (long long)out_size; i += blockDim.x) out[i] = loss;
}

extern "C" void kernel_launch(void* const* d_in, const int* in_sizes, int n_in,
                              void* d_out, int out_size) {
    const float* z  = (const float*)d_in[0];
    const float* cb = (const float*)d_in[1];
    if (n_in >= 2 && in_sizes[0] == KCODES * DDIM && in_sizes[1] == NROWS * DDIM) {
        z = (const float*)d_in[1]; cb = (const float*)d_in[0];
    }
    float* out = (float*)d_out;
    cudaFuncSetAttribute(vq_kernel, cudaFuncAttributeMaxDynamicSharedMemorySize, SMEM_VQ);

    zquant_kernel<<<8192, 256>>>(z);
    cbprep_kernel<<<4, 256>>>(cb);
    vq_kernel<<<444, 256, SMEM_VQ>>>();
    resolve_kernel<<<512, 256>>>(z, cb);
    gather_kernel<<<512, 256>>>(z, cb, out);
    finalize_kernel<<<1, 512>>>(out, out_size);
}

// round 16
// speedup vs baseline: 21.6888x; 1.1350x over previous
#include <cuda_runtime.h>
#include <cstdint>

#define NROWS  65536
#define DDIM   256
#define KCODES 1024
#define NT64   1024          // tiles of 64 rows
#define MARGIN 2e-3f
#define FINF   3.4e38f
#define RING   28

typedef unsigned int u32; typedef unsigned long long u64;

__device__ __align__(16) u32 gAq[NT64 * 64 * 64];     // [tile64][k4][row] int8x4
__device__ __align__(16) u32 gBq[16 * 64 * 64];       // [chunk64][k4][code] int8x4
__device__ float g_esq[KCODES];
__device__ float g_ce[KCODES];        // -2 * s_e
__device__ float g_zs[NROWS];         // s_z per row
__device__ int   g_idx[NROWS];
__device__ int   g_amb[NROWS];
__device__ float g_ambv[NROWS];
__device__ u64   g_cand[(size_t)NROWS * RING];
__device__ int   g_ccnt[NROWS];
__device__ int   g_amb_n;
__device__ int   g_tilectr;
__device__ float g_partial[512];

__device__ __forceinline__ u32 smem_u32(const void* p) {
    u32 a; asm("{ .reg .u64 t; cvta.to.shared.u64 t, %1; cvt.u32.u64 %0, t; }" : "=r"(a) : "l"(p));
    return a;
}
__device__ __forceinline__ void cpasync16(u32 dst, const void* src) {
    u64 g = (u64)__cvta_generic_to_global(src);
    asm volatile("cp.async.cg.shared.global [%0], [%1], 16;" :: "r"(dst), "l"(g) : "memory");
}
__device__ __forceinline__ int dp4a(u32 a, u32 b, int c) {
    int r;
    asm("dp4a.s32.s32 %0, %1, %2, %3;" : "=r"(r) : "r"(a), "r"(b), "r"(c));
    return r;
}
__device__ __forceinline__ u32 q4(float a, float b, float c, float d, float inv) {
    int qa = max(-127, min(127, __float2int_rn(a * inv)));
    int qb = max(-127, min(127, __float2int_rn(b * inv)));
    int qc = max(-127, min(127, __float2int_rn(c * inv)));
    int qd = max(-127, min(127, __float2int_rn(d * inv)));
    return (u32)(qa & 255) | ((u32)(qb & 255) << 8) | ((u32)(qc & 255) << 16) | ((u32)(qd & 255) << 24);
}
__device__ __forceinline__ u32 fenc(float f) {
    u32 b = __float_as_uint(f);
    return (b & 0x80000000u) ? ~b : (b | 0x80000000u);
}

// ---------------- prep ----------------
__global__ void zquant_kernel(const float* __restrict__ z) {
    int w = (blockIdx.x * blockDim.x + threadIdx.x) >> 5, lane = threadIdx.x & 31;
    const float* row = z + (size_t)w * DDIM;
    float4 v0 = __ldg((const float4*)(row + lane * 8));
    float4 v1 = __ldg((const float4*)(row + lane * 8 + 4));
    float mx = fmaxf(fmaxf(fmaxf(fabsf(v0.x), fabsf(v0.y)), fmaxf(fabsf(v0.z), fabsf(v0.w))),
                     fmaxf(fmaxf(fabsf(v1.x), fabsf(v1.y)), fmaxf(fabsf(v1.z), fabsf(v1.w))));
    #pragma unroll
    for (int m = 16; m; m >>= 1) mx = fmaxf(mx, __shfl_xor_sync(0xffffffffu, mx, m));
    mx = fmaxf(mx, 1e-30f);
    float inv = 127.0f / mx;
    if (lane == 0) { g_zs[w] = mx / 127.0f; g_ccnt[w] = 0; }
    u32 p0 = q4(v0.x, v0.y, v0.z, v0.w, inv);
    u32 p1 = q4(v1.x, v1.y, v1.z, v1.w, inv);
    int tile = w >> 6, rloc = w & 63;
    gAq[((size_t)tile * 64 + lane * 2 + 0) * 64 + rloc] = p0;
    gAq[((size_t)tile * 64 + lane * 2 + 1) * 64 + rloc] = p1;
}

// thread per code: EXACT serial esq + scale + quantize; zero counters
__global__ void cbprep_kernel(const float* __restrict__ cb) {
    int k = blockIdx.x * blockDim.x + threadIdx.x;
    if (k == 0) { g_amb_n = 0; g_tilectr = 0; }
    if (k >= KCODES) return;
    const float* row = cb + (size_t)k * DDIM;
    float s = 0.f, mx = 1e-30f;
    #pragma unroll 8
    for (int d = 0; d < DDIM; d += 4) {
        float4 v = *(const float4*)&row[d];
        s = __fadd_rn(s, __fmul_rn(v.x, v.x)); s = __fadd_rn(s, __fmul_rn(v.y, v.y));
        s = __fadd_rn(s, __fmul_rn(v.z, v.z)); s = __fadd_rn(s, __fmul_rn(v.w, v.w));
        mx = fmaxf(mx, fmaxf(fmaxf(fabsf(v.x), fabsf(v.y)), fmaxf(fabsf(v.z), fabsf(v.w))));
    }
    g_esq[k] = s;
    g_ce[k] = -2.0f * (mx / 127.0f);
    float inv = 127.0f / mx;
    int chunk = k >> 6, kloc = k & 63;
    #pragma unroll 8
    for (int d = 0; d < DDIM; d += 4) {
        float4 v = *(const float4*)&row[d];
        gBq[(chunk * 64 + (d >> 2)) * 64 + kloc] = q4(v.x, v.y, v.z, v.w, inv);
    }
}

// ---------------- main dp4a GEMM + candidate ring (persistent, M=64) -------
#define SM_A     0                      // 64 k4 x 64 rows x 4B = 16384
#define SM_B(s)  (16384 + (s) * 16384)  // 2 stages
#define SM_TILE  49152
#define SMEM_VQ  49408

__global__ __launch_bounds__(256, 4) void vq_kernel() {
    extern __shared__ unsigned char sm[];
    u32 sb = smem_u32(sm);
    int* tilebuf = (int*)(sm + SM_TILE);
    const int t = threadIdx.x, tx = t & 15, ty = t >> 4;

    for (;;) {
        if (t == 0) *tilebuf = atomicAdd(&g_tilectr, 1);
        __syncthreads();                    // publish tile; prior-tile smem reads done
        const int tile = *tilebuf;
        if (tile >= NT64) break;

        // A (16KB) + B chunk 0 (16KB) as group G0
        for (int i = t; i < 1024; i += 256)
            cpasync16(sb + SM_A + i * 16, (const char*)gAq + (size_t)tile * 16384 + i * 16);
        for (int i = t; i < 1024; i += 256)
            cpasync16(sb + SM_B(0) + i * 16, (const char*)gBq + i * 16);
        asm volatile("cp.async.commit_group;" ::: "memory");

        float sz[4];
        #pragma unroll
        for (int i = 0; i < 4; i++) sz[i] = g_zs[tile * 64 + ty * 4 + i];
        float m1[4], m2[4]; int i1[4];
        #pragma unroll
        for (int i = 0; i < 4; i++) { m1[i] = FINF; m2[i] = FINF; i1[i] = 0x7fffffff; }

        for (int c = 0; c < 16; c++) {
            asm volatile("cp.async.wait_group 0;" ::: "memory");
            __syncthreads();                // stage c ready; prior stage reads done
            if (c < 15) {                   // prefetch AFTER the sync (overwrite-safe)
                u32 dst = sb + SM_B((c + 1) & 1);
                const char* src = (const char*)gBq + (size_t)(c + 1) * 16384;
                for (int i = t; i < 1024; i += 256) cpasync16(dst + i * 16, src + i * 16);
                asm volatile("cp.async.commit_group;" ::: "memory");
            }

            int acc[4][4];
            #pragma unroll
            for (int i = 0; i < 4; i++)
                #pragma unroll
                for (int j = 0; j < 4; j++) acc[i][j] = 0;

            const unsigned char* bst = (const unsigned char*)sm + SM_B(c & 1);
            #pragma unroll 8
            for (int r = 0; r < 32; r++) {
                int k4 = r * 2;
                uint4 a0 = *(const uint4*)(sm + SM_A + k4 * 256 + ty * 16);
                uint4 a1 = *(const uint4*)(sm + SM_A + (k4 + 1) * 256 + ty * 16);
                uint4 b0 = *(const uint4*)(bst + k4 * 256 + tx * 16);        // codes tx*4..+3
                uint4 b1 = *(const uint4*)(bst + (k4 + 1) * 256 + tx * 16);
                u32 ar0[4] = {a0.x, a0.y, a0.z, a0.w};
                u32 ar1[4] = {a1.x, a1.y, a1.z, a1.w};
                u32 br0[4] = {b0.x, b0.y, b0.z, b0.w};
                u32 br1[4] = {b1.x, b1.y, b1.z, b1.w};
                #pragma unroll
                for (int j = 0; j < 4; j++)
                    #pragma unroll
                    for (int i = 0; i < 4; i++) {
                        acc[i][j] = dp4a(ar0[i], br0[j], acc[i][j]);
                        acc[i][j] = dp4a(ar1[i], br1[j], acc[i][j]);
                    }
            }
            // pass 1: local top-2 (codes c*64 + tx*4 + j, contiguous per thread)
            float4 ce4 = __ldg((const float4*)&g_ce[c * 64 + tx * 4]);
            float4 eq4 = __ldg((const float4*)&g_esq[c * 64 + tx * 4]);
            float cearr[4] = {ce4.x, ce4.y, ce4.z, ce4.w};
            float eqarr[4] = {eq4.x, eq4.y, eq4.z, eq4.w};
            #pragma unroll
            for (int j = 0; j < 4; j++) {
                int code = c * 64 + tx * 4 + j;
                #pragma unroll
                for (int i = 0; i < 4; i++) {
                    float d = fmaf((float)acc[i][j] * cearr[j], sz[i], eqarr[j]);
                    bool p1 = d < m1[i], p2 = d < m2[i];
                    i1[i] = p1 ? code : i1[i];
                    m2[i] = p2 ? (p1 ? m1[i] : d) : m2[i];
                    m1[i] = p1 ? d : m1[i];
                }
            }
            // pass 2: row-min via half-warp shfl, recompute d from live acc, append
            #pragma unroll
            for (int i = 0; i < 4; i++) {
                float rm = m1[i];
                #pragma unroll
                for (int msk = 1; msk <= 8; msk <<= 1)
                    rm = fminf(rm, __shfl_xor_sync(0xffffffffu, rm, msk));
                float thr = rm + MARGIN;
                int row = tile * 64 + ty * 4 + i;
                #pragma unroll
                for (int j = 0; j < 4; j++) {
                    float d = fmaf((float)acc[i][j] * cearr[j], sz[i], eqarr[j]);
                    if (d <= thr) {
                        int code = c * 64 + tx * 4 + j;
                        int pos = atomicAdd(&g_ccnt[row], 1);
                        if (pos < RING)
                            g_cand[(size_t)row * RING + pos] =
                                ((u64)__float_as_uint(d) << 32) | (u32)code;
                    }
                }
            }
        }
        // final per-row top-2 merge across tx lanes via shfl (lexicographic)
        #pragma unroll
        for (int i = 0; i < 4; i++) {
            float v1 = m1[i], v2 = m2[i]; int a1 = i1[i];
            #pragma unroll
            for (int msk = 1; msk <= 8; msk <<= 1) {
                float ov1 = __shfl_xor_sync(0xffffffffu, v1, msk);
                float ov2 = __shfl_xor_sync(0xffffffffu, v2, msk);
                int   oa1 = __shfl_xor_sync(0xffffffffu, a1, msk);
                if (ov1 < v1 || (ov1 == v1 && oa1 < a1)) {
                    v2 = fminf(v1, ov2); v1 = ov1; a1 = oa1;
                } else {
                    v2 = fminf(v2, ov1);
                }
            }
            if (tx == 0) {
                int row = tile * 64 + ty * 4 + i;
                g_idx[row] = a1;
                if (v2 - v1 <= MARGIN) {
                    int p = atomicAdd(&g_amb_n, 1);
                    g_amb[p] = row; g_ambv[p] = v1;
                }
            }
        }
    }
}

// ---------------- exact resolution: 8-lane group per ambiguous row ---------
__global__ __launch_bounds__(256) void resolve_kernel(const float* __restrict__ z,
                                                      const float* __restrict__ cb) {
    int n = g_amb_n;
    int gid = (blockIdx.x * blockDim.x + threadIdx.x) >> 3, l8 = threadIdx.x & 7;
    int ng = (gridDim.x * blockDim.x) >> 3;
    for (int a = gid; a < n; a += ng) {
        int row = g_amb[a];
        float v1 = g_ambv[a];
        int cnt = g_ccnt[row];
        const float* zr = z + (size_t)row * DDIM;
        float bestv = FINF; int besti = 0x7fffffff;
        if (cnt <= RING) {
            for (int ci = l8; ci < cnt; ci += 8) {
                u64 e = g_cand[(size_t)row * RING + ci];
                float da = __uint_as_float((u32)(e >> 32));
                if (da > v1 + MARGIN) continue;
                int code = (int)(u32)e;
                const float* er = cb + (size_t)code * DDIM;
                float cr = 0.f, zq = 0.f;
                #pragma unroll 8
                for (int d = 0; d < DDIM; d += 4) {
                    float4 zv = __ldg((const float4*)(zr + d));
                    float4 ev = __ldg((const float4*)(er + d));
                    zq = __fadd_rn(zq, __fmul_rn(zv.x, zv.x)); zq = __fadd_rn(zq, __fmul_rn(zv.y, zv.y));
                    zq = __fadd_rn(zq, __fmul_rn(zv.z, zv.z)); zq = __fadd_rn(zq, __fmul_rn(zv.w, zv.w));
                    cr = fmaf(zv.x, ev.x, cr); cr = fmaf(zv.y, ev.y, cr);
                    cr = fmaf(zv.z, ev.z, cr); cr = fmaf(zv.w, ev.w, cr);
                }
                float dist = __fadd_rn(__fsub_rn(zq, __fmul_rn(2.f, cr)), __ldg(&g_esq[code]));
                if (dist < bestv || (dist == bestv && code < besti)) { bestv = dist; besti = code; }
            }
        } else {
            float zq = 0.f;
            #pragma unroll 8
            for (int d = 0; d < DDIM; d += 4) {
                float4 zv = __ldg((const float4*)(zr + d));
                zq = __fadd_rn(zq, __fmul_rn(zv.x, zv.x)); zq = __fadd_rn(zq, __fmul_rn(zv.y, zv.y));
                zq = __fadd_rn(zq, __fmul_rn(zv.z, zv.z)); zq = __fadd_rn(zq, __fmul_rn(zv.w, zv.w));
            }
            for (int k = l8; k < KCODES; k += 8) {
                const float* er = cb + (size_t)k * DDIM;
                float cr = 0.f;
                #pragma unroll 8
                for (int d = 0; d < DDIM; d += 4) {
                    float4 zv = __ldg((const float4*)(zr + d));
                    float4 ev = __ldg((const float4*)(er + d));
                    cr = fmaf(zv.x, ev.x, cr); cr = fmaf(zv.y, ev.y, cr);
                    cr = fmaf(zv.z, ev.z, cr); cr = fmaf(zv.w, ev.w, cr);
                }
                float dist = __fadd_rn(__fsub_rn(zq, __fmul_rn(2.f, cr)), __ldg(&g_esq[k]));
                if (dist < bestv) { bestv = dist; besti = k; }   // ascending k
            }
        }
        // 8-lane group argmin (xor 1,2,4 stay within the group)
        #pragma unroll
        for (int msk = 1; msk <= 4; msk <<= 1) {
            float ov = __shfl_xor_sync(0xffffffffu, bestv, msk);
            int   oi = __shfl_xor_sync(0xffffffffu, besti, msk);
            if (ov < bestv || (ov == bestv && oi < besti)) { bestv = ov; besti = oi; }
        }
        if (l8 == 0) g_idx[row] = besti;
    }
}

// ---------------- gather + loss ----------------
__global__ __launch_bounds__(256) void gather_kernel(const float* __restrict__ z,
                                                     const float* __restrict__ cb,
                                                     float* __restrict__ out) {
    __shared__ int sidx[128]; __shared__ float red[256];
    int t = threadIdx.x, rowbase = blockIdx.x * 128;
    if (t < 128) sidx[t] = g_idx[rowbase + t];
    __syncthreads();
    float lsum = 0.f;
    #pragma unroll 8
    for (int r = 0; r < 128; r++) {
        int idx = sidx[r];
        float zq = cb[(size_t)idx * DDIM + t];
        float ze = z[(size_t)(rowbase + r) * DDIM + t];
        out[(size_t)(rowbase + r) * DDIM + t] = zq;
        float df = zq - ze; lsum = fmaf(df, df, lsum);
    }
    red[t] = lsum; __syncthreads();
    for (int s = 128; s; s >>= 1) { if (t < s) red[t] += red[t + s]; __syncthreads(); }
    if (t == 0) g_partial[blockIdx.x] = red[0];
}

__global__ void finalize_kernel(float* __restrict__ out, int out_size) {
    __shared__ float red[512];
    int t = threadIdx.x;
    red[t] = g_partial[t];
    __syncthreads();
    for (int s = 256; s; s >>= 1) { if (t < s) red[t] += red[t + s]; __syncthreads(); }
    float loss = red[0] / (float)((long long)NROWS * DDIM);
    const long long base = (long long)NROWS * DDIM;
    for (long long i = base + t; i < (long long)out_size; i += blockDim.x) out[i] = loss;
}

extern "C" void kernel_launch(void* const* d_in, const int* in_sizes, int n_in,
                              void* d_out, int out_size) {
    const float* z  = (const float*)d_in[0];
    const float* cb = (const float*)d_in[1];
    if (n_in >= 2 && in_sizes[0] == KCODES * DDIM && in_sizes[1] == NROWS * DDIM) {
        z = (const float*)d_in[1]; cb = (const float*)d_in[0];
    }
    float* out = (float*)d_out;
    cudaFuncSetAttribute(vq_kernel, cudaFuncAttributeMaxDynamicSharedMemorySize, SMEM_VQ);

    zquant_kernel<<<8192, 256>>>(z);
    cbprep_kernel<<<4, 256>>>(cb);
    vq_kernel<<<592, 256, SMEM_VQ>>>();
    resolve_kernel<<<592, 256>>>(z, cb);
    gather_kernel<<<512, 256>>>(z, cb, out);
    finalize_kernel<<<1, 512>>>(out, out_size);
}

// round 17
// speedup vs baseline: 23.1202x; 1.0660x over previous
#include <cuda_runtime.h>
#include <cstdint>

#define NROWS  65536
#define DDIM   256
#define KCODES 1024
#define NT64   1024          // tiles of 64 rows
#define MARGIN 2e-3f
#define FINF   3.4e38f
#define RING   28

typedef unsigned int u32; typedef unsigned long long u64;

__device__ __align__(16) u32 gAq[NT64 * 64 * 64];     // [tile64][k4][row] int8x4
__device__ __align__(16) u32 gBq[16 * 64 * 64];       // [chunk64][k4][code] int8x4
__device__ float g_esq[KCODES];
__device__ float g_ce[KCODES];        // -2 * s_e
__device__ float g_zs[NROWS];         // s_z per row
__device__ int   g_idx[NROWS];
__device__ int   g_amb[NROWS];
__device__ float g_ambv[NROWS];
__device__ u64   g_cand[(size_t)NROWS * RING];
__device__ int   g_ccnt[NROWS];
__device__ int   g_amb_n;
__device__ int   g_tilectr;
__device__ float g_partial[1024];

__device__ __forceinline__ u32 smem_u32(const void* p) {
    u32 a; asm("{ .reg .u64 t; cvta.to.shared.u64 t, %1; cvt.u32.u64 %0, t; }" : "=r"(a) : "l"(p));
    return a;
}
__device__ __forceinline__ void cpasync16(u32 dst, const void* src) {
    u64 g = (u64)__cvta_generic_to_global(src);
    asm volatile("cp.async.cg.shared.global [%0], [%1], 16;" :: "r"(dst), "l"(g) : "memory");
}
__device__ __forceinline__ int dp4a(u32 a, u32 b, int c) {
    int r;
    asm("dp4a.s32.s32 %0, %1, %2, %3;" : "=r"(r) : "r"(a), "r"(b), "r"(c));
    return r;
}
__device__ __forceinline__ u32 q4(float a, float b, float c, float d, float inv) {
    int qa = max(-127, min(127, __float2int_rn(a * inv)));
    int qb = max(-127, min(127, __float2int_rn(b * inv)));
    int qc = max(-127, min(127, __float2int_rn(c * inv)));
    int qd = max(-127, min(127, __float2int_rn(d * inv)));
    return (u32)(qa & 255) | ((u32)(qb & 255) << 8) | ((u32)(qc & 255) << 16) | ((u32)(qd & 255) << 24);
}

// ---------------- prep ----------------
__global__ void zquant_kernel(const float* __restrict__ z) {
    int w = (blockIdx.x * blockDim.x + threadIdx.x) >> 5, lane = threadIdx.x & 31;
    const float* row = z + (size_t)w * DDIM;
    float4 v0 = __ldg((const float4*)(row + lane * 8));
    float4 v1 = __ldg((const float4*)(row + lane * 8 + 4));
    float mx = fmaxf(fmaxf(fmaxf(fabsf(v0.x), fabsf(v0.y)), fmaxf(fabsf(v0.z), fabsf(v0.w))),
                     fmaxf(fmaxf(fabsf(v1.x), fabsf(v1.y)), fmaxf(fabsf(v1.z), fabsf(v1.w))));
    #pragma unroll
    for (int m = 16; m; m >>= 1) mx = fmaxf(mx, __shfl_xor_sync(0xffffffffu, mx, m));
    mx = fmaxf(mx, 1e-30f);
    float inv = 127.0f / mx;
    if (lane == 0) { g_zs[w] = mx / 127.0f; g_ccnt[w] = 0; }
    u32 p0 = q4(v0.x, v0.y, v0.z, v0.w, inv);
    u32 p1 = q4(v1.x, v1.y, v1.z, v1.w, inv);
    int tile = w >> 6, rloc = w & 63;
    gAq[((size_t)tile * 64 + lane * 2 + 0) * 64 + rloc] = p0;
    gAq[((size_t)tile * 64 + lane * 2 + 1) * 64 + rloc] = p1;
}

// thread per code: EXACT serial esq + scale + quantize; zero counters
__global__ void cbprep_kernel(const float* __restrict__ cb) {
    int k = blockIdx.x * blockDim.x + threadIdx.x;
    if (k == 0) { g_amb_n = 0; g_tilectr = 0; }
    if (k >= KCODES) return;
    const float* row = cb + (size_t)k * DDIM;
    float s = 0.f, mx = 1e-30f;
    #pragma unroll 8
    for (int d = 0; d < DDIM; d += 4) {
        float4 v = *(const float4*)&row[d];
        s = __fadd_rn(s, __fmul_rn(v.x, v.x)); s = __fadd_rn(s, __fmul_rn(v.y, v.y));
        s = __fadd_rn(s, __fmul_rn(v.z, v.z)); s = __fadd_rn(s, __fmul_rn(v.w, v.w));
        mx = fmaxf(mx, fmaxf(fmaxf(fabsf(v.x), fabsf(v.y)), fmaxf(fabsf(v.z), fabsf(v.w))));
    }
    g_esq[k] = s;
    g_ce[k] = -2.0f * (mx / 127.0f);
    float inv = 127.0f / mx;
    int chunk = k >> 6, kloc = k & 63;
    #pragma unroll 8
    for (int d = 0; d < DDIM; d += 4) {
        float4 v = *(const float4*)&row[d];
        gBq[(chunk * 64 + (d >> 2)) * 64 + kloc] = q4(v.x, v.y, v.z, v.w, inv);
    }
}

// ---------------- main dp4a GEMM + candidate ring (persistent, M=64) -------
#define SM_A     0                      // 64 k4 x 64 rows x 4B = 16384
#define SM_B(s)  (16384 + (s) * 16384)  // 2 stages
#define SM_TILE  49152
#define SMEM_VQ  49408

__global__ __launch_bounds__(256, 4) void vq_kernel() {
    extern __shared__ unsigned char sm[];
    u32 sb = smem_u32(sm);
    int* tilebuf = (int*)(sm + SM_TILE);
    const int t = threadIdx.x, tx = t & 15, ty = t >> 4;

    for (;;) {
        if (t == 0) *tilebuf = atomicAdd(&g_tilectr, 1);
        __syncthreads();                    // publish tile; prior-tile smem reads done
        const int tile = *tilebuf;
        if (tile >= NT64) break;

        // A (16KB) + B chunk 0 (16KB) as group G0
        for (int i = t; i < 1024; i += 256)
            cpasync16(sb + SM_A + i * 16, (const char*)gAq + (size_t)tile * 16384 + i * 16);
        for (int i = t; i < 1024; i += 256)
            cpasync16(sb + SM_B(0) + i * 16, (const char*)gBq + i * 16);
        asm volatile("cp.async.commit_group;" ::: "memory");

        float sz[4];
        #pragma unroll
        for (int i = 0; i < 4; i++) sz[i] = g_zs[tile * 64 + ty * 4 + i];
        float m1[4], m2[4]; int i1[4];
        #pragma unroll
        for (int i = 0; i < 4; i++) { m1[i] = FINF; m2[i] = FINF; i1[i] = 0x7fffffff; }

        for (int c = 0; c < 16; c++) {
            asm volatile("cp.async.wait_group 0;" ::: "memory");
            __syncthreads();                // stage c ready; prior stage reads done
            if (c < 15) {                   // prefetch AFTER the sync (overwrite-safe)
                u32 dst = sb + SM_B((c + 1) & 1);
                const char* src = (const char*)gBq + (size_t)(c + 1) * 16384;
                for (int i = t; i < 1024; i += 256) cpasync16(dst + i * 16, src + i * 16);
                asm volatile("cp.async.commit_group;" ::: "memory");
            }

            int acc[4][4];
            #pragma unroll
            for (int i = 0; i < 4; i++)
                #pragma unroll
                for (int j = 0; j < 4; j++) acc[i][j] = 0;

            const unsigned char* bst = (const unsigned char*)sm + SM_B(c & 1);
            #pragma unroll 8
            for (int r = 0; r < 32; r++) {
                int k4 = r * 2;
                uint4 a0 = *(const uint4*)(sm + SM_A + k4 * 256 + ty * 16);
                uint4 a1 = *(const uint4*)(sm + SM_A + (k4 + 1) * 256 + ty * 16);
                uint4 b0 = *(const uint4*)(bst + k4 * 256 + tx * 16);        // codes tx*4..+3
                uint4 b1 = *(const uint4*)(bst + (k4 + 1) * 256 + tx * 16);
                u32 ar0[4] = {a0.x, a0.y, a0.z, a0.w};
                u32 ar1[4] = {a1.x, a1.y, a1.z, a1.w};
                u32 br0[4] = {b0.x, b0.y, b0.z, b0.w};
                u32 br1[4] = {b1.x, b1.y, b1.z, b1.w};
                #pragma unroll
                for (int j = 0; j < 4; j++)
                    #pragma unroll
                    for (int i = 0; i < 4; i++) {
                        acc[i][j] = dp4a(ar0[i], br0[j], acc[i][j]);
                        acc[i][j] = dp4a(ar1[i], br1[j], acc[i][j]);
                    }
            }
            // pass 1: local top-2 (codes c*64 + tx*4 + j, contiguous per thread)
            float4 ce4 = __ldg((const float4*)&g_ce[c * 64 + tx * 4]);
            float4 eq4 = __ldg((const float4*)&g_esq[c * 64 + tx * 4]);
            float cearr[4] = {ce4.x, ce4.y, ce4.z, ce4.w};
            float eqarr[4] = {eq4.x, eq4.y, eq4.z, eq4.w};
            #pragma unroll
            for (int j = 0; j < 4; j++) {
                int code = c * 64 + tx * 4 + j;
                #pragma unroll
                for (int i = 0; i < 4; i++) {
                    float d = fmaf((float)acc[i][j] * cearr[j], sz[i], eqarr[j]);
                    bool p1 = d < m1[i], p2 = d < m2[i];
                    i1[i] = p1 ? code : i1[i];
                    m2[i] = p2 ? (p1 ? m1[i] : d) : m2[i];
                    m1[i] = p1 ? d : m1[i];
                }
            }
            // pass 2: row-min via half-warp shfl, recompute d from live acc, append
            #pragma unroll
            for (int i = 0; i < 4; i++) {
                float rm = m1[i];
                #pragma unroll
                for (int msk = 1; msk <= 8; msk <<= 1)
                    rm = fminf(rm, __shfl_xor_sync(0xffffffffu, rm, msk));
                float thr = rm + MARGIN;
                int row = tile * 64 + ty * 4 + i;
                #pragma unroll
                for (int j = 0; j < 4; j++) {
                    float d = fmaf((float)acc[i][j] * cearr[j], sz[i], eqarr[j]);
                    if (d <= thr) {
                        int code = c * 64 + tx * 4 + j;
                        int pos = atomicAdd(&g_ccnt[row], 1);
                        if (pos < RING)
                            g_cand[(size_t)row * RING + pos] =
                                ((u64)__float_as_uint(d) << 32) | (u32)code;
                    }
                }
            }
        }
        // final per-row top-2 merge across tx lanes via shfl (lexicographic)
        #pragma unroll
        for (int i = 0; i < 4; i++) {
            float v1 = m1[i], v2 = m2[i]; int a1 = i1[i];
            #pragma unroll
            for (int msk = 1; msk <= 8; msk <<= 1) {
                float ov1 = __shfl_xor_sync(0xffffffffu, v1, msk);
                float ov2 = __shfl_xor_sync(0xffffffffu, v2, msk);
                int   oa1 = __shfl_xor_sync(0xffffffffu, a1, msk);
                if (ov1 < v1 || (ov1 == v1 && oa1 < a1)) {
                    v2 = fminf(v1, ov2); v1 = ov1; a1 = oa1;
                } else {
                    v2 = fminf(v2, ov1);
                }
            }
            if (tx == 0) {
                int row = tile * 64 + ty * 4 + i;
                g_idx[row] = a1;
                if (v2 - v1 <= MARGIN) {
                    int p = atomicAdd(&g_amb_n, 1);
                    g_amb[p] = row; g_ambv[p] = v1;
                }
            }
        }
    }
}

// ---------------- exact resolution: 4-lane group per ambiguous row ---------
__global__ __launch_bounds__(256) void resolve_kernel(const float* __restrict__ z,
                                                      const float* __restrict__ cb) {
    int n = g_amb_n;
    int gid = (blockIdx.x * blockDim.x + threadIdx.x) >> 2, l4 = threadIdx.x & 3;
    int ng = (gridDim.x * blockDim.x) >> 2;
    for (int a = gid; a < n; a += ng) {
        int row = g_amb[a];
        float v1 = g_ambv[a];
        int cnt = g_ccnt[row];
        const float* zr = z + (size_t)row * DDIM;
        float bestv = FINF; int besti = 0x7fffffff;
        if (cnt <= RING) {
            for (int ci = l4; ci < cnt; ci += 4) {
                u64 e = g_cand[(size_t)row * RING + ci];
                float da = __uint_as_float((u32)(e >> 32));
                if (da > v1 + MARGIN) continue;
                int code = (int)(u32)e;
                const float* er = cb + (size_t)code * DDIM;
                float cr = 0.f, zq = 0.f;
                #pragma unroll 8
                for (int d = 0; d < DDIM; d += 4) {
                    float4 zv = __ldg((const float4*)(zr + d));
                    float4 ev = __ldg((const float4*)(er + d));
                    zq = __fadd_rn(zq, __fmul_rn(zv.x, zv.x)); zq = __fadd_rn(zq, __fmul_rn(zv.y, zv.y));
                    zq = __fadd_rn(zq, __fmul_rn(zv.z, zv.z)); zq = __fadd_rn(zq, __fmul_rn(zv.w, zv.w));
                    cr = fmaf(zv.x, ev.x, cr); cr = fmaf(zv.y, ev.y, cr);
                    cr = fmaf(zv.z, ev.z, cr); cr = fmaf(zv.w, ev.w, cr);
                }
                float dist = __fadd_rn(__fsub_rn(zq, __fmul_rn(2.f, cr)), __ldg(&g_esq[code]));
                if (dist < bestv || (dist == bestv && code < besti)) { bestv = dist; besti = code; }
            }
        } else {
            float zq = 0.f;
            #pragma unroll 8
            for (int d = 0; d < DDIM; d += 4) {
                float4 zv = __ldg((const float4*)(zr + d));
                zq = __fadd_rn(zq, __fmul_rn(zv.x, zv.x)); zq = __fadd_rn(zq, __fmul_rn(zv.y, zv.y));
                zq = __fadd_rn(zq, __fmul_rn(zv.z, zv.z)); zq = __fadd_rn(zq, __fmul_rn(zv.w, zv.w));
            }
            for (int k = l4; k < KCODES; k += 4) {
                const float* er = cb + (size_t)k * DDIM;
                float cr = 0.f;
                #pragma unroll 8
                for (int d = 0; d < DDIM; d += 4) {
                    float4 zv = __ldg((const float4*)(zr + d));
                    float4 ev = __ldg((const float4*)(er + d));
                    cr = fmaf(zv.x, ev.x, cr); cr = fmaf(zv.y, ev.y, cr);
                    cr = fmaf(zv.z, ev.z, cr); cr = fmaf(zv.w, ev.w, cr);
                }
                float dist = __fadd_rn(__fsub_rn(zq, __fmul_rn(2.f, cr)), __ldg(&g_esq[k]));
                if (dist < bestv) { bestv = dist; besti = k; }   // ascending k
            }
        }
        // 4-lane group argmin (xor 1,2 stay within the group)
        #pragma unroll
        for (int msk = 1; msk <= 2; msk <<= 1) {
            float ov = __shfl_xor_sync(0xffffffffu, bestv, msk);
            int   oi = __shfl_xor_sync(0xffffffffu, besti, msk);
            if (ov < bestv || (ov == bestv && oi < besti)) { bestv = ov; besti = oi; }
        }
        if (l4 == 0) g_idx[row] = besti;
    }
}

// ---------------- gather + loss (float4 lanes, 64 rows/block) --------------
__global__ __launch_bounds__(256) void gather_kernel(const float* __restrict__ z,
                                                     const float* __restrict__ cb,
                                                     float* __restrict__ out) {
    __shared__ int sidx[64]; __shared__ float red[256];
    int t = threadIdx.x, rowbase = blockIdx.x * 64;
    int grp = t >> 6, l64 = t & 63;        // 4 groups x 64 threads; 16B dim chunk each
    if (t < 64) sidx[t] = g_idx[rowbase + t];
    __syncthreads();
    float lsum = 0.f;
    #pragma unroll 4
    for (int rr = 0; rr < 16; rr++) {
        int r = grp * 16 + rr;
        int idx = sidx[r];
        float4 zq = __ldg((const float4*)&cb[(size_t)idx * DDIM + l64 * 4]);
        float4 ze = __ldg((const float4*)&z[(size_t)(rowbase + r) * DDIM + l64 * 4]);
        *(float4*)&out[(size_t)(rowbase + r) * DDIM + l64 * 4] = zq;
        float dx = zq.x - ze.x, dy = zq.y - ze.y, dz = zq.z - ze.z, dw = zq.w - ze.w;
        lsum = fmaf(dx, dx, lsum); lsum = fmaf(dy, dy, lsum);
        lsum = fmaf(dz, dz, lsum); lsum = fmaf(dw, dw, lsum);
    }
    red[t] = lsum; __syncthreads();
    for (int s = 128; s; s >>= 1) { if (t < s) red[t] += red[t + s]; __syncthreads(); }
    if (t == 0) g_partial[blockIdx.x] = red[0];
}

__global__ void finalize_kernel(float* __restrict__ out, int out_size) {
    __shared__ float red[1024];
    int t = threadIdx.x;
    red[t] = g_partial[t] + g_partial[t + 512];
    __syncthreads();
    for (int s = 256; s; s >>= 1) { if (t < s) red[t] += red[t + s]; __syncthreads(); }
    float loss = red[0] / (float)((long long)NROWS * DDIM);
    const long long base = (long long)NROWS * DDIM;
    for (long long i = base + t; i < (long long)out_size; i += blockDim.x) out[i] = loss;
}

extern "C" void kernel_launch(void* const* d_in, const int* in_sizes, int n_in,
                              void* d_out, int out_size) {
    const float* z  = (const float*)d_in[0];
    const float* cb = (const float*)d_in[1];
    if (n_in >= 2 && in_sizes[0] == KCODES * DDIM && in_sizes[1] == NROWS * DDIM) {
        z = (const float*)d_in[1]; cb = (const float*)d_in[0];
    }
    float* out = (float*)d_out;
    cudaFuncSetAttribute(vq_kernel, cudaFuncAttributeMaxDynamicSharedMemorySize, SMEM_VQ);

    zquant_kernel<<<8192, 256>>>(z);
    cbprep_kernel<<<4, 256>>>(cb);
    vq_kernel<<<592, 256, SMEM_VQ>>>();
    resolve_kernel<<<592, 256>>>(z, cb);
    gather_kernel<<<1024, 256>>>(z, cb, out);
    finalize_kernel<<<1, 512>>>(out, out_size);
}